// round 1
// baseline (speedup 1.0000x reference)
#include <cuda_runtime.h>
#include <cuda_bf16.h>
#include <mma.h>

using namespace nvcuda;

// Problem constants
#define BB   2
#define LL   2048
#define DD   512
#define KK   32
#define GG   32
#define HH   8
#define DHH  64
#define CTX  65        // 1 + K + G
#define BL   (BB*LL)   // 4096

// Scratch buffers (device globals: no allocation allowed)
__device__ float g_Q   [BL * DD];
__device__ float g_K   [BL * DD];
__device__ float g_V   [BL * DD];
__device__ float g_attn[BL * DD];
__device__ float g_Kg  [BB * GG * DD];
__device__ float g_Vg  [BB * GG * DD];

// ---------------------------------------------------------------------------
// tf32 WMMA GEMM: C[M,512] = A[M,512] @ W[512,512] (+ optional bias[512])
// 64x64 tile per block, BK=32, 128 threads (4 warps, 2x2, each 32x32)
// ---------------------------------------------------------------------------
__global__ __launch_bounds__(128)
void sgemm_tf32(const float* __restrict__ A, const float* __restrict__ W,
                const float* __restrict__ bias, float* __restrict__ C)
{
    const int N = 512;
    // As[64][36] then Bs[32][68]; epilogue reuses the whole buffer as Cs[64][68]
    __shared__ __align__(16) float smem[64*36 + 32*68];
    float (*As)[36] = reinterpret_cast<float(*)[36]>(smem);
    float (*Bs)[68] = reinterpret_cast<float(*)[68]>(smem + 64*36);
    float (*Cs)[68] = reinterpret_cast<float(*)[68]>(smem);

    const int tid = threadIdx.x;
    const int wid = tid >> 5;
    const int m0 = blockIdx.y * 64;
    const int n0 = blockIdx.x * 64;
    const int warp_m = wid >> 1;
    const int warp_n = wid & 1;

    wmma::fragment<wmma::accumulator, 16, 16, 8, float> acc[2][2];
    #pragma unroll
    for (int i = 0; i < 2; i++)
        #pragma unroll
        for (int j = 0; j < 2; j++)
            wmma::fill_fragment(acc[i][j], 0.0f);

    for (int k0 = 0; k0 < 512; k0 += 32) {
        // Load A tile: 64 rows x 32 cols (8 float4 per row)
        // Load W tile: 32 rows x 64 cols (16 float4 per row)
        #pragma unroll
        for (int i = 0; i < 4; i++) {
            int lin = tid + i * 128;
            int r  = lin >> 3, c  = (lin & 7) << 2;
            float4 va = *reinterpret_cast<const float4*>(
                &A[(size_t)(m0 + r) * 512 + k0 + c]);
            As[r][c + 0] = wmma::__float_to_tf32(va.x);
            As[r][c + 1] = wmma::__float_to_tf32(va.y);
            As[r][c + 2] = wmma::__float_to_tf32(va.z);
            As[r][c + 3] = wmma::__float_to_tf32(va.w);
            int rb = lin >> 4, cb = (lin & 15) << 2;
            float4 vb = *reinterpret_cast<const float4*>(
                &W[(size_t)(k0 + rb) * N + n0 + cb]);
            Bs[rb][cb + 0] = wmma::__float_to_tf32(vb.x);
            Bs[rb][cb + 1] = wmma::__float_to_tf32(vb.y);
            Bs[rb][cb + 2] = wmma::__float_to_tf32(vb.z);
            Bs[rb][cb + 3] = wmma::__float_to_tf32(vb.w);
        }
        __syncthreads();

        #pragma unroll
        for (int kk = 0; kk < 4; kk++) {
            wmma::fragment<wmma::matrix_a, 16, 16, 8, wmma::precision::tf32,
                           wmma::row_major> af[2];
            wmma::fragment<wmma::matrix_b, 16, 16, 8, wmma::precision::tf32,
                           wmma::row_major> bf[2];
            wmma::load_matrix_sync(af[0], &As[warp_m * 32     ][kk * 8], 36);
            wmma::load_matrix_sync(af[1], &As[warp_m * 32 + 16][kk * 8], 36);
            wmma::load_matrix_sync(bf[0], &Bs[kk * 8][warp_n * 32     ], 68);
            wmma::load_matrix_sync(bf[1], &Bs[kk * 8][warp_n * 32 + 16], 68);
            #pragma unroll
            for (int i = 0; i < 2; i++)
                #pragma unroll
                for (int j = 0; j < 2; j++)
                    wmma::mma_sync(acc[i][j], af[i], bf[j], acc[i][j]);
        }
        __syncthreads();
    }

    // Epilogue: stage into smem, add bias, vectorized store
    #pragma unroll
    for (int i = 0; i < 2; i++)
        #pragma unroll
        for (int j = 0; j < 2; j++)
            wmma::store_matrix_sync(&Cs[warp_m * 32 + i * 16][warp_n * 32 + j * 16],
                                    acc[i][j], 68, wmma::mem_row_major);
    __syncthreads();

    #pragma unroll
    for (int i = 0; i < 8; i++) {
        int lin = tid + i * 128;          // 1024 float4 = 64x64 floats
        int r = lin >> 4, c4 = (lin & 15) << 2;
        float4 v = *reinterpret_cast<const float4*>(&Cs[r][c4]);
        if (bias) {
            v.x += bias[n0 + c4 + 0];
            v.y += bias[n0 + c4 + 1];
            v.z += bias[n0 + c4 + 2];
            v.w += bias[n0 + c4 + 3];
        }
        *reinterpret_cast<float4*>(&C[(size_t)(m0 + r) * N + n0 + c4]) = v;
    }
}

// ---------------------------------------------------------------------------
// Gather attention: one block per (b,l), one warp per head.
// logits over 65 contexts (self + 32 kNN + 32 globals), gaussian dist bias on
// local contexts, flat learned bias on globals, softmax, weighted V sum.
// ---------------------------------------------------------------------------
__global__ __launch_bounds__(256)
void attn_kernel(const float* __restrict__ Q,   const float* __restrict__ Ksp,
                 const float* __restrict__ Vsp, const float* __restrict__ Kg,
                 const float* __restrict__ Vg,  const int*   __restrict__ topk,
                 const float* __restrict__ dist,
                 const float* __restrict__ log_sigma,
                 const float* __restrict__ gbias_p,
                 float* __restrict__ outb)
{
    const int bl   = blockIdx.x;
    const int b    = bl >> 11;            // L = 2048
    const int tid  = threadIdx.x;
    const int h    = tid >> 5;
    const int lane = tid & 31;

    __shared__ const float* kp[CTX];
    __shared__ const float* vp[CTX];
    __shared__ float dist2[33];
    __shared__ float logits[HH][68];

    if (tid < CTX) {
        int c = tid;
        const float *kq, *vq;
        if (c == 0) {
            kq = Ksp + (size_t)bl * DD;
            vq = Vsp + (size_t)bl * DD;
        } else if (c < 33) {
            int r = b * LL + topk[(size_t)bl * KK + (c - 1)];
            kq = Ksp + (size_t)r * DD;
            vq = Vsp + (size_t)r * DD;
        } else {
            int r = b * GG + (c - 33);
            kq = Kg + (size_t)r * DD;
            vq = Vg + (size_t)r * DD;
        }
        kp[c] = kq;
        vp[c] = vq;
        if (c < 33) {
            float d = (c == 0) ? 0.0f : dist[(size_t)bl * KK + (c - 1)];
            dist2[c] = d * d;
        }
    }
    __syncthreads();

    const float inv2s = 0.5f * __expf(-2.0f * log_sigma[h]);  // 1/(2*sigma^2)
    const float gb    = *gbias_p;
    const float scale = 0.125f;                               // 64^-0.5
    const int   off   = h * DHH + lane * 2;

    const float2 q2 = *reinterpret_cast<const float2*>(Q + (size_t)bl * DD + off);

    // logits
    #pragma unroll 4
    for (int c = 0; c < CTX; c++) {
        float2 kk = *reinterpret_cast<const float2*>(kp[c] + off);
        float s = q2.x * kk.x + q2.y * kk.y;
        #pragma unroll
        for (int d = 16; d; d >>= 1)
            s += __shfl_xor_sync(0xffffffffu, s, d);
        if (lane == 0)
            logits[h][c] = s * scale + ((c < 33) ? -dist2[c] * inv2s : gb);
    }
    __syncwarp();

    // softmax over 65 entries (per-warp)
    float l0 = logits[h][lane];
    float l1 = logits[h][lane + 32];
    float l2 = (lane == 0) ? logits[h][64] : -1e30f;
    float m = fmaxf(fmaxf(l0, l1), l2);
    #pragma unroll
    for (int d = 16; d; d >>= 1)
        m = fmaxf(m, __shfl_xor_sync(0xffffffffu, m, d));
    float e0 = __expf(l0 - m);
    float e1 = __expf(l1 - m);
    float e2 = (lane == 0) ? __expf(l2 - m) : 0.0f;
    float s = e0 + e1 + e2;
    #pragma unroll
    for (int d = 16; d; d >>= 1)
        s += __shfl_xor_sync(0xffffffffu, s, d);
    float inv = 1.0f / s;
    logits[h][lane]      = e0 * inv;
    logits[h][lane + 32] = e1 * inv;
    if (lane == 0) logits[h][64] = e2 * inv;
    __syncwarp();

    // weighted V sum
    float2 acc = make_float2(0.0f, 0.0f);
    #pragma unroll 4
    for (int c = 0; c < CTX; c++) {
        float  p = logits[h][c];
        float2 v = *reinterpret_cast<const float2*>(vp[c] + off);
        acc.x += p * v.x;
        acc.y += p * v.y;
    }
    *reinterpret_cast<float2*>(outb + (size_t)bl * DD + off) = acc;
}

// ---------------------------------------------------------------------------
extern "C" void kernel_launch(void* const* d_in, const int* in_sizes, int n_in,
                              void* d_out, int out_size)
{
    const float* spatial = (const float*)d_in[0];
    const int*   topk    = (const int*)  d_in[1];
    const float* dist    = (const float*)d_in[2];
    const float* glat    = (const float*)d_in[3];
    const float* Wq      = (const float*)d_in[4];
    const float* Wk      = (const float*)d_in[5];
    const float* Wv      = (const float*)d_in[6];
    const float* Wo      = (const float*)d_in[7];
    const float* bo      = (const float*)d_in[8];
    const float* lsig    = (const float*)d_in[9];
    const float* gbias   = (const float*)d_in[10];
    float* out = (float*)d_out;

    float *Qp, *Kp, *Vp, *Ap, *Kgp, *Vgp;
    cudaGetSymbolAddress((void**)&Qp,  g_Q);
    cudaGetSymbolAddress((void**)&Kp,  g_K);
    cudaGetSymbolAddress((void**)&Vp,  g_V);
    cudaGetSymbolAddress((void**)&Ap,  g_attn);
    cudaGetSymbolAddress((void**)&Kgp, g_Kg);
    cudaGetSymbolAddress((void**)&Vgp, g_Vg);

    dim3 big(8, BL / 64);     // N tiles x M tiles for M=4096
    dim3 small(8, 1);         // M=64 (global latents)

    sgemm_tf32<<<big,   128>>>(spatial, Wq, nullptr, Qp);
    sgemm_tf32<<<big,   128>>>(spatial, Wk, nullptr, Kp);
    sgemm_tf32<<<big,   128>>>(spatial, Wv, nullptr, Vp);
    sgemm_tf32<<<small, 128>>>(glat,    Wk, nullptr, Kgp);
    sgemm_tf32<<<small, 128>>>(glat,    Wv, nullptr, Vgp);

    attn_kernel<<<BL, 256>>>(Qp, Kp, Vp, Kgp, Vgp, topk, dist, lsig, gbias, Ap);

    sgemm_tf32<<<big, 128>>>(Ap, Wo, bo, out);
}

// round 2
// speedup vs baseline: 1.1634x; 1.1634x over previous
#include <cuda_runtime.h>
#include <cuda_bf16.h>
#include <mma.h>

using namespace nvcuda;

// Problem constants
#define BB   2
#define LL   2048
#define DD   512
#define KK   32
#define GG   32
#define HH   8
#define DHH  64
#define CTX  65        // 1 + K + G
#define BL   (BB*LL)   // 4096

// Scratch buffers (device globals: no allocation allowed)
__device__ float g_Q   [BL * DD];
__device__ float g_K   [BL * DD];
__device__ float g_V   [BL * DD];
__device__ float g_attn[BL * DD];
__device__ float g_Kg  [BB * GG * DD];
__device__ float g_Vg  [BB * GG * DD];

// ---------------------------------------------------------------------------
// GEMM tile core: C[0:rows, n0:n0+64] = A[0:rows, 0:512] @ W[512, 512]
// BM=128, BN=64, BK=32, 256 threads (8 warps, 4x2, each warp 32x32 via
// 2x2 wmma tf32 m16n16k8). Register double-buffered global loads.
// A and C are pre-offset to the M-tile base row by the caller.
// ---------------------------------------------------------------------------
__device__ __forceinline__ void gemm_tile_core(
    const float* __restrict__ A, const float* __restrict__ W,
    float* __restrict__ C, const float* __restrict__ bias,
    int n0, int rows)
{
    // As[128][36] + Bs[32][68]; bias epilogue reuses buffer as Cs[128][68]
    __shared__ __align__(16) float smem[128 * 68];
    float (*As)[36] = reinterpret_cast<float(*)[36]>(smem);
    float (*Bs)[68] = reinterpret_cast<float(*)[68]>(smem + 128 * 36);
    float (*Cs)[68] = reinterpret_cast<float(*)[68]>(smem);

    const int tid    = threadIdx.x;
    const int wid    = tid >> 5;
    const int warp_m = wid >> 1;     // 0..3
    const int warp_n = wid & 1;      // 0..1

    // Per-thread load coordinates
    // A tile: 128x32 = 1024 float4, 4 per thread
    // B tile:  32x64 =  512 float4, 2 per thread
    int a_r[4], a_c[4], b_r[2], b_c[2];
    #pragma unroll
    for (int i = 0; i < 4; i++) {
        int lin = tid + i * 256;
        int r = lin >> 3;
        a_r[i] = (rows == 64) ? (r & 63) : r;   // clamp for 64-row aux tile
        a_c[i] = (lin & 7) << 2;
    }
    #pragma unroll
    for (int i = 0; i < 2; i++) {
        int lin = tid + i * 256;
        b_r[i] = lin >> 4;
        b_c[i] = (lin & 15) << 2;
    }

    wmma::fragment<wmma::accumulator, 16, 16, 8, float> acc[2][2];
    #pragma unroll
    for (int i = 0; i < 2; i++)
        #pragma unroll
        for (int j = 0; j < 2; j++)
            wmma::fill_fragment(acc[i][j], 0.0f);

    float4 ra[4], rb[2];
    // Preload tile k0=0
    #pragma unroll
    for (int i = 0; i < 4; i++)
        ra[i] = *reinterpret_cast<const float4*>(&A[(size_t)a_r[i] * 512 + a_c[i]]);
    #pragma unroll
    for (int i = 0; i < 2; i++)
        rb[i] = *reinterpret_cast<const float4*>(&W[(size_t)b_r[i] * 512 + n0 + b_c[i]]);

    for (int k0 = 0; k0 < 512; k0 += 32) {
        __syncthreads();   // previous compute done, smem free
        #pragma unroll
        for (int i = 0; i < 4; i++) {
            As[a_r[i] >= 0 ? ((tid + i * 256) >> 3) : 0][a_c[i] + 0] = wmma::__float_to_tf32(ra[i].x);
            As[(tid + i * 256) >> 3][a_c[i] + 1] = wmma::__float_to_tf32(ra[i].y);
            As[(tid + i * 256) >> 3][a_c[i] + 2] = wmma::__float_to_tf32(ra[i].z);
            As[(tid + i * 256) >> 3][a_c[i] + 3] = wmma::__float_to_tf32(ra[i].w);
        }
        #pragma unroll
        for (int i = 0; i < 2; i++) {
            Bs[b_r[i]][b_c[i] + 0] = wmma::__float_to_tf32(rb[i].x);
            Bs[b_r[i]][b_c[i] + 1] = wmma::__float_to_tf32(rb[i].y);
            Bs[b_r[i]][b_c[i] + 2] = wmma::__float_to_tf32(rb[i].z);
            Bs[b_r[i]][b_c[i] + 3] = wmma::__float_to_tf32(rb[i].w);
        }
        __syncthreads();   // smem ready

        // Prefetch next tile into registers (hidden behind MMA work)
        if (k0 + 32 < 512) {
            int kn = k0 + 32;
            #pragma unroll
            for (int i = 0; i < 4; i++)
                ra[i] = *reinterpret_cast<const float4*>(&A[(size_t)a_r[i] * 512 + kn + a_c[i]]);
            #pragma unroll
            for (int i = 0; i < 2; i++)
                rb[i] = *reinterpret_cast<const float4*>(&W[(size_t)(kn + b_r[i]) * 512 + n0 + b_c[i]]);
        }

        #pragma unroll
        for (int kk = 0; kk < 4; kk++) {
            wmma::fragment<wmma::matrix_a, 16, 16, 8, wmma::precision::tf32,
                           wmma::row_major> af[2];
            wmma::fragment<wmma::matrix_b, 16, 16, 8, wmma::precision::tf32,
                           wmma::row_major> bf[2];
            wmma::load_matrix_sync(af[0], &As[warp_m * 32     ][kk * 8], 36);
            wmma::load_matrix_sync(af[1], &As[warp_m * 32 + 16][kk * 8], 36);
            wmma::load_matrix_sync(bf[0], &Bs[kk * 8][warp_n * 32     ], 68);
            wmma::load_matrix_sync(bf[1], &Bs[kk * 8][warp_n * 32 + 16], 68);
            #pragma unroll
            for (int i = 0; i < 2; i++)
                #pragma unroll
                for (int j = 0; j < 2; j++)
                    wmma::mma_sync(acc[i][j], af[i], bf[j], acc[i][j]);
        }
    }

    if (bias == nullptr) {
        // Direct global store (no bias)
        if (rows == 64 && warp_m >= 2) return;
        #pragma unroll
        for (int i = 0; i < 2; i++)
            #pragma unroll
            for (int j = 0; j < 2; j++)
                wmma::store_matrix_sync(
                    &C[(size_t)(warp_m * 32 + i * 16) * 512 + n0 + warp_n * 32 + j * 16],
                    acc[i][j], 512, wmma::mem_row_major);
    } else {
        // Stage via smem, add bias, vectorized store
        __syncthreads();
        #pragma unroll
        for (int i = 0; i < 2; i++)
            #pragma unroll
            for (int j = 0; j < 2; j++)
                wmma::store_matrix_sync(
                    &Cs[warp_m * 32 + i * 16][warp_n * 32 + j * 16],
                    acc[i][j], 68, wmma::mem_row_major);
        __syncthreads();
        #pragma unroll
        for (int i = 0; i < 8; i++) {
            int lin = tid + i * 256;          // 2048 float4 = 128x64 floats
            int r = lin >> 4, c4 = (lin & 15) << 2;
            float4 v = *reinterpret_cast<const float4*>(&Cs[r][c4]);
            v.x += bias[n0 + c4 + 0];
            v.y += bias[n0 + c4 + 1];
            v.z += bias[n0 + c4 + 2];
            v.w += bias[n0 + c4 + 3];
            *reinterpret_cast<float4*>(&C[(size_t)r * 512 + n0 + c4]) = v;
        }
    }
}

// Fused Q/K/V projection (+ global-latent K/V) in one launch.
// grid = (8, 33, 3): x = N tile, y = M tile (y==32 -> glat aux), z = which W
__global__ __launch_bounds__(256)
void qkv_gemm(const float* __restrict__ spatial, const float* __restrict__ glat,
              const float* __restrict__ Wq, const float* __restrict__ Wk,
              const float* __restrict__ Wv,
              float* __restrict__ Q, float* __restrict__ K, float* __restrict__ V,
              float* __restrict__ Kg, float* __restrict__ Vg)
{
    const int z = blockIdx.z, y = blockIdx.y;
    const float* W = (z == 0) ? Wq : (z == 1) ? Wk : Wv;
    const float* A;
    float* C;
    int rows;
    if (y < 32) {
        A = spatial + (size_t)y * 128 * 512;
        C = ((z == 0) ? Q : (z == 1) ? K : V) + (size_t)y * 128 * 512;
        rows = 128;
    } else {
        if (z == 0) return;
        A = glat;
        C = (z == 1) ? Kg : Vg;
        rows = 64;
    }
    gemm_tile_core(A, W, C, nullptr, blockIdx.x * 64, rows);
}

// Output projection with bias. grid = (8, 32)
__global__ __launch_bounds__(256)
void out_gemm(const float* __restrict__ A, const float* __restrict__ W,
              const float* __restrict__ bias, float* __restrict__ C)
{
    gemm_tile_core(A + (size_t)blockIdx.y * 128 * 512, W,
                   C + (size_t)blockIdx.y * 128 * 512, bias,
                   blockIdx.x * 64, 128);
}

// ---------------------------------------------------------------------------
// Gather attention: one block per (b,l), one warp per head.
// ---------------------------------------------------------------------------
__global__ __launch_bounds__(256)
void attn_kernel(const float* __restrict__ Q,   const float* __restrict__ Ksp,
                 const float* __restrict__ Vsp, const float* __restrict__ Kg,
                 const float* __restrict__ Vg,  const int*   __restrict__ topk,
                 const float* __restrict__ dist,
                 const float* __restrict__ log_sigma,
                 const float* __restrict__ gbias_p,
                 float* __restrict__ outb)
{
    const int bl   = blockIdx.x;
    const int b    = bl >> 11;            // L = 2048
    const int tid  = threadIdx.x;
    const int h    = tid >> 5;
    const int lane = tid & 31;

    __shared__ const float* kp[CTX];
    __shared__ const float* vp[CTX];
    __shared__ float dist2[33];
    __shared__ float logits[HH][68];

    if (tid < CTX) {
        int c = tid;
        const float *kq, *vq;
        if (c == 0) {
            kq = Ksp + (size_t)bl * DD;
            vq = Vsp + (size_t)bl * DD;
        } else if (c < 33) {
            int r = b * LL + topk[(size_t)bl * KK + (c - 1)];
            kq = Ksp + (size_t)r * DD;
            vq = Vsp + (size_t)r * DD;
        } else {
            int r = b * GG + (c - 33);
            kq = Kg + (size_t)r * DD;
            vq = Vg + (size_t)r * DD;
        }
        kp[c] = kq;
        vp[c] = vq;
        if (c < 33) {
            float d = (c == 0) ? 0.0f : dist[(size_t)bl * KK + (c - 1)];
            dist2[c] = d * d;
        }
    }
    __syncthreads();

    const float inv2s = 0.5f * __expf(-2.0f * log_sigma[h]);  // 1/(2*sigma^2)
    const float gb    = *gbias_p;
    const float scale = 0.125f;                               // 64^-0.5
    const int   off   = h * DHH + lane * 2;

    const float2 q2 = *reinterpret_cast<const float2*>(Q + (size_t)bl * DD + off);

    // logits
    #pragma unroll 4
    for (int c = 0; c < CTX; c++) {
        float2 kk = *reinterpret_cast<const float2*>(kp[c] + off);
        float s = q2.x * kk.x + q2.y * kk.y;
        #pragma unroll
        for (int d = 16; d; d >>= 1)
            s += __shfl_xor_sync(0xffffffffu, s, d);
        if (lane == 0)
            logits[h][c] = s * scale + ((c < 33) ? -dist2[c] * inv2s : gb);
    }
    __syncwarp();

    // softmax over 65 entries (per-warp)
    float l0 = logits[h][lane];
    float l1 = logits[h][lane + 32];
    float l2 = (lane == 0) ? logits[h][64] : -1e30f;
    float m = fmaxf(fmaxf(l0, l1), l2);
    #pragma unroll
    for (int d = 16; d; d >>= 1)
        m = fmaxf(m, __shfl_xor_sync(0xffffffffu, m, d));
    float e0 = __expf(l0 - m);
    float e1 = __expf(l1 - m);
    float e2 = (lane == 0) ? __expf(l2 - m) : 0.0f;
    float s = e0 + e1 + e2;
    #pragma unroll
    for (int d = 16; d; d >>= 1)
        s += __shfl_xor_sync(0xffffffffu, s, d);
    float inv = 1.0f / s;
    logits[h][lane]      = e0 * inv;
    logits[h][lane + 32] = e1 * inv;
    if (lane == 0) logits[h][64] = e2 * inv;
    __syncwarp();

    // weighted V sum
    float2 acc = make_float2(0.0f, 0.0f);
    #pragma unroll 4
    for (int c = 0; c < CTX; c++) {
        float  p = logits[h][c];
        float2 v = *reinterpret_cast<const float2*>(vp[c] + off);
        acc.x += p * v.x;
        acc.y += p * v.y;
    }
    *reinterpret_cast<float2*>(outb + (size_t)bl * DD + off) = acc;
}

// ---------------------------------------------------------------------------
extern "C" void kernel_launch(void* const* d_in, const int* in_sizes, int n_in,
                              void* d_out, int out_size)
{
    const float* spatial = (const float*)d_in[0];
    const int*   topk    = (const int*)  d_in[1];
    const float* dist    = (const float*)d_in[2];
    const float* glat    = (const float*)d_in[3];
    const float* Wq      = (const float*)d_in[4];
    const float* Wk      = (const float*)d_in[5];
    const float* Wv      = (const float*)d_in[6];
    const float* Wo      = (const float*)d_in[7];
    const float* bo      = (const float*)d_in[8];
    const float* lsig    = (const float*)d_in[9];
    const float* gbias   = (const float*)d_in[10];
    float* out = (float*)d_out;

    float *Qp, *Kp, *Vp, *Ap, *Kgp, *Vgp;
    cudaGetSymbolAddress((void**)&Qp,  g_Q);
    cudaGetSymbolAddress((void**)&Kp,  g_K);
    cudaGetSymbolAddress((void**)&Vp,  g_V);
    cudaGetSymbolAddress((void**)&Ap,  g_attn);
    cudaGetSymbolAddress((void**)&Kgp, g_Kg);
    cudaGetSymbolAddress((void**)&Vgp, g_Vg);

    dim3 qkv_grid(8, 33, 3);
    qkv_gemm<<<qkv_grid, 256>>>(spatial, glat, Wq, Wk, Wv,
                                Qp, Kp, Vp, Kgp, Vgp);

    attn_kernel<<<BL, 256>>>(Qp, Kp, Vp, Kgp, Vgp, topk, dist, lsig, gbias, Ap);

    dim3 out_grid(8, 32);
    out_gemm<<<out_grid, 256>>>(Ap, Wo, bo, out);
}

// round 6
// speedup vs baseline: 1.1875x; 1.0207x over previous
#include <cuda_runtime.h>
#include <cuda_bf16.h>
#include <mma.h>
#include <cstdint>

using namespace nvcuda;

// Problem constants
#define BB   2
#define LL   2048
#define DD   512
#define KK   32
#define GG   32
#define HH   8
#define DHH  64
#define CTX  65        // 1 + K + G
#define BL   (BB*LL)   // 4096

// Scratch buffers (device globals: no allocation allowed)
__device__ float g_Q   [BL * DD];
__device__ float g_K   [BL * DD];
__device__ float g_V   [BL * DD];
__device__ float g_attn[BL * DD];
__device__ float g_Kg  [BB * GG * DD];
__device__ float g_Vg  [BB * GG * DD];
// tf32-rounded copies of GEMM inputs
__device__ float g_sp_cv[BL * DD];
__device__ float g_gl_cv[BB * GG * DD];
__device__ float g_Wq_cv[DD * DD];
__device__ float g_Wk_cv[DD * DD];
__device__ float g_Wv_cv[DD * DD];
__device__ float g_Wo_cv[DD * DD];

// ---------------------------------------------------------------------------
// tf32 RN rounding helper (cvt.rna.tf32.f32 needs a .b32 destination)
// ---------------------------------------------------------------------------
__device__ __forceinline__ float rn_tf32(float x) {
    uint32_t u;
    asm("cvt.rna.tf32.f32 %0, %1;" : "=r"(u) : "f"(x));
    return __uint_as_float(u);
}

// One kernel converts all 6 input arrays (blockIdx.y selects segment)
__global__ __launch_bounds__(256)
void to_tf32_all(const float* s0, float* d0, int n0,
                 const float* s1, float* d1, int n1,
                 const float* s2, float* d2, int n2,
                 const float* s3, float* d3, int n3,
                 const float* s4, float* d4, int n4,
                 const float* s5, float* d5, int n5)
{
    const float* src; float* dst; int n4cnt;
    switch (blockIdx.y) {
        case 0: src = s0; dst = d0; n4cnt = n0; break;
        case 1: src = s1; dst = d1; n4cnt = n1; break;
        case 2: src = s2; dst = d2; n4cnt = n2; break;
        case 3: src = s3; dst = d3; n4cnt = n3; break;
        case 4: src = s4; dst = d4; n4cnt = n4; break;
        default: src = s5; dst = d5; n4cnt = n5; break;
    }
    int stride = gridDim.x * blockDim.x;
    for (int i = blockIdx.x * blockDim.x + threadIdx.x; i < n4cnt; i += stride) {
        float4 v = reinterpret_cast<const float4*>(src)[i];
        v.x = rn_tf32(v.x); v.y = rn_tf32(v.y);
        v.z = rn_tf32(v.z); v.w = rn_tf32(v.w);
        reinterpret_cast<float4*>(dst)[i] = v;
    }
}

// ---------------------------------------------------------------------------
// cp.async helpers
// ---------------------------------------------------------------------------
__device__ __forceinline__ void cp_async16(void* smem_dst, const void* gsrc) {
    unsigned int sa = (unsigned int)__cvta_generic_to_shared(smem_dst);
    asm volatile("cp.async.cg.shared.global [%0], [%1], 16;\n" :: "r"(sa), "l"(gsrc));
}
__device__ __forceinline__ void cp_commit() {
    asm volatile("cp.async.commit_group;\n" ::);
}
template <int N>
__device__ __forceinline__ void cp_wait() {
    asm volatile("cp.async.wait_group %0;\n" :: "n"(N));
}

// ---------------------------------------------------------------------------
// GEMM core: C[0:rows, n0:n0+128] = A[0:rows, 0:512] @ W[512,512] (+bias)
// BM=128, BN=128, BK=32, 3-stage cp.async pipeline, 256 threads.
// Warp grid 4x2, warp tile 32x64 (2x4 wmma tf32 m16n16k8 accumulators).
// Inputs must already be tf32-representable (pre-rounded) fp32.
// ---------------------------------------------------------------------------
constexpr int ASTR = 36;    // As row stride (floats)
constexpr int BSTR = 132;   // Bs row stride (floats)
constexpr int STAGE_FLOATS = 128 * ASTR + 32 * BSTR;   // 8832
constexpr int GEMM_SMEM = 3 * STAGE_FLOATS * 4;        // 105984 bytes

__device__ __forceinline__ void issue_stage(
    float* stage, const float* __restrict__ A, const float* __restrict__ W,
    int n0, int k0, int tid, int rmask)
{
    float* As = stage;
    float* Bs = stage + 128 * ASTR;
    #pragma unroll
    for (int t = 0; t < 4; t++) {
        int lin = tid + t * 256;
        int r = lin >> 3, c = (lin & 7) << 2;              // A: 128x32
        cp_async16(&As[r * ASTR + c], &A[(size_t)(r & rmask) * 512 + k0 + c]);
        int rb = lin >> 5, cb = (lin & 31) << 2;           // B: 32x128
        cp_async16(&Bs[rb * BSTR + cb], &W[(size_t)(k0 + rb) * 512 + n0 + cb]);
    }
}

__device__ __forceinline__ void gemm_core(
    const float* __restrict__ A, const float* __restrict__ W,
    float* __restrict__ C, const float* __restrict__ bias,
    int n0, int rows)
{
    extern __shared__ __align__(16) float dsmem[];
    const int tid    = threadIdx.x;
    const int wid    = tid >> 5;
    const int warp_m = wid >> 1;     // 0..3 -> rows warp_m*32
    const int warp_n = wid & 1;      // 0..1 -> cols warp_n*64
    const int rmask  = (rows == 64) ? 63 : 127;

    wmma::fragment<wmma::accumulator, 16, 16, 8, float> acc[2][4];
    #pragma unroll
    for (int i = 0; i < 2; i++)
        #pragma unroll
        for (int j = 0; j < 4; j++)
            wmma::fill_fragment(acc[i][j], 0.0f);

    issue_stage(dsmem,                A, W, n0, 0,  tid, rmask); cp_commit();
    issue_stage(dsmem + STAGE_FLOATS, A, W, n0, 32, tid, rmask); cp_commit();

    for (int it = 0; it < 16; it++) {
        cp_wait<1>();
        __syncthreads();
        if (it + 2 < 16)
            issue_stage(dsmem + ((it + 2) % 3) * STAGE_FLOATS, A, W,
                        n0, (it + 2) * 32, tid, rmask);
        cp_commit();   // commit every iter (possibly empty) to keep counts aligned

        float* As = dsmem + (it % 3) * STAGE_FLOATS;
        float* Bs = As + 128 * ASTR;
        #pragma unroll
        for (int kk = 0; kk < 4; kk++) {
            wmma::fragment<wmma::matrix_a, 16, 16, 8, wmma::precision::tf32,
                           wmma::row_major> af[2];
            wmma::fragment<wmma::matrix_b, 16, 16, 8, wmma::precision::tf32,
                           wmma::row_major> bf[4];
            wmma::load_matrix_sync(af[0], &As[(warp_m * 32     ) * ASTR + kk * 8], ASTR);
            wmma::load_matrix_sync(af[1], &As[(warp_m * 32 + 16) * ASTR + kk * 8], ASTR);
            #pragma unroll
            for (int j = 0; j < 4; j++)
                wmma::load_matrix_sync(bf[j], &Bs[(kk * 8) * BSTR + warp_n * 64 + j * 16], BSTR);
            #pragma unroll
            for (int i = 0; i < 2; i++)
                #pragma unroll
                for (int j = 0; j < 4; j++)
                    wmma::mma_sync(acc[i][j], af[i], bf[j], acc[i][j]);
        }
        __syncthreads();
    }

    if (bias == nullptr) {
        if (rows == 64 && warp_m >= 2) return;
        #pragma unroll
        for (int i = 0; i < 2; i++)
            #pragma unroll
            for (int j = 0; j < 4; j++)
                wmma::store_matrix_sync(
                    &C[(size_t)(warp_m * 32 + i * 16) * 512 + n0 + warp_n * 64 + j * 16],
                    acc[i][j], 512, wmma::mem_row_major);
    } else {
        // stage via smem (reuse pipeline buffer), add bias, vector store
        float (*Cs)[BSTR] = reinterpret_cast<float(*)[BSTR]>(dsmem);
        #pragma unroll
        for (int i = 0; i < 2; i++)
            #pragma unroll
            for (int j = 0; j < 4; j++)
                wmma::store_matrix_sync(
                    &Cs[warp_m * 32 + i * 16][warp_n * 64 + j * 16],
                    acc[i][j], BSTR, wmma::mem_row_major);
        __syncthreads();
        #pragma unroll
        for (int i = 0; i < 16; i++) {
            int lin = tid + i * 256;            // 4096 float4 = 128x128 floats
            int r = lin >> 5, c4 = (lin & 31) << 2;
            float4 v = *reinterpret_cast<const float4*>(&Cs[r][c4]);
            v.x += bias[n0 + c4 + 0];
            v.y += bias[n0 + c4 + 1];
            v.z += bias[n0 + c4 + 2];
            v.w += bias[n0 + c4 + 3];
            *reinterpret_cast<float4*>(&C[(size_t)r * 512 + n0 + c4]) = v;
        }
    }
}

// Fused Q/K/V projection (+ global-latent K/V). grid = (4, 33, 3)
__global__ __launch_bounds__(256, 1)
void qkv_gemm(const float* __restrict__ spatial, const float* __restrict__ glat,
              const float* __restrict__ Wq, const float* __restrict__ Wk,
              const float* __restrict__ Wv,
              float* __restrict__ Q, float* __restrict__ K, float* __restrict__ V,
              float* __restrict__ Kg, float* __restrict__ Vg)
{
    const int z = blockIdx.z, y = blockIdx.y;
    const float* W = (z == 0) ? Wq : (z == 1) ? Wk : Wv;
    if (y < 32) {
        const float* A = spatial + (size_t)y * 128 * 512;
        float* C = ((z == 0) ? Q : (z == 1) ? K : V) + (size_t)y * 128 * 512;
        gemm_core(A, W, C, nullptr, blockIdx.x * 128, 128);
    } else {
        if (z == 0) return;
        gemm_core(glat, W, (z == 1) ? Kg : Vg, nullptr, blockIdx.x * 128, 64);
    }
}

// Output projection with bias. grid = (4, 32)
__global__ __launch_bounds__(256, 1)
void out_gemm(const float* __restrict__ A, const float* __restrict__ W,
              const float* __restrict__ bias, float* __restrict__ C)
{
    gemm_core(A + (size_t)blockIdx.y * 128 * 512, W,
              C + (size_t)blockIdx.y * 128 * 512, bias,
              blockIdx.x * 128, 128);
}

// ---------------------------------------------------------------------------
// Gather attention: one block per (b,l), one warp per head.
// Output rounded to tf32 so out_gemm needs no conversion.
// ---------------------------------------------------------------------------
__global__ __launch_bounds__(256)
void attn_kernel(const float* __restrict__ Q,   const float* __restrict__ Ksp,
                 const float* __restrict__ Vsp, const float* __restrict__ Kg,
                 const float* __restrict__ Vg,  const int*   __restrict__ topk,
                 const float* __restrict__ dist,
                 const float* __restrict__ log_sigma,
                 const float* __restrict__ gbias_p,
                 float* __restrict__ outb)
{
    const int bl   = blockIdx.x;
    const int b    = bl >> 11;            // L = 2048
    const int tid  = threadIdx.x;
    const int h    = tid >> 5;
    const int lane = tid & 31;

    __shared__ const float* kp[CTX];
    __shared__ const float* vp[CTX];
    __shared__ float dist2[33];
    __shared__ float logits[HH][68];

    if (tid < CTX) {
        int c = tid;
        const float *kq, *vq;
        if (c == 0) {
            kq = Ksp + (size_t)bl * DD;
            vq = Vsp + (size_t)bl * DD;
        } else if (c < 33) {
            int r = b * LL + topk[(size_t)bl * KK + (c - 1)];
            kq = Ksp + (size_t)r * DD;
            vq = Vsp + (size_t)r * DD;
        } else {
            int r = b * GG + (c - 33);
            kq = Kg + (size_t)r * DD;
            vq = Vg + (size_t)r * DD;
        }
        kp[c] = kq;
        vp[c] = vq;
        if (c < 33) {
            float d = (c == 0) ? 0.0f : dist[(size_t)bl * KK + (c - 1)];
            dist2[c] = d * d;
        }
    }
    __syncthreads();

    const float inv2s = 0.5f * __expf(-2.0f * log_sigma[h]);  // 1/(2*sigma^2)
    const float gb    = *gbias_p;
    const float scale = 0.125f;                               // 64^-0.5
    const int   off   = h * DHH + lane * 2;

    const float2 q2 = *reinterpret_cast<const float2*>(Q + (size_t)bl * DD + off);

    // logits
    #pragma unroll 4
    for (int c = 0; c < CTX; c++) {
        float2 kk = *reinterpret_cast<const float2*>(kp[c] + off);
        float s = q2.x * kk.x + q2.y * kk.y;
        #pragma unroll
        for (int d = 16; d; d >>= 1)
            s += __shfl_xor_sync(0xffffffffu, s, d);
        if (lane == 0)
            logits[h][c] = s * scale + ((c < 33) ? -dist2[c] * inv2s : gb);
    }
    __syncwarp();

    // softmax over 65 entries (per-warp)
    float l0 = logits[h][lane];
    float l1 = logits[h][lane + 32];
    float l2 = (lane == 0) ? logits[h][64] : -1e30f;
    float m = fmaxf(fmaxf(l0, l1), l2);
    #pragma unroll
    for (int d = 16; d; d >>= 1)
        m = fmaxf(m, __shfl_xor_sync(0xffffffffu, m, d));
    float e0 = __expf(l0 - m);
    float e1 = __expf(l1 - m);
    float e2 = (lane == 0) ? __expf(l2 - m) : 0.0f;
    float s = e0 + e1 + e2;
    #pragma unroll
    for (int d = 16; d; d >>= 1)
        s += __shfl_xor_sync(0xffffffffu, s, d);
    float inv = 1.0f / s;
    logits[h][lane]      = e0 * inv;
    logits[h][lane + 32] = e1 * inv;
    if (lane == 0) logits[h][64] = e2 * inv;
    __syncwarp();

    // weighted V sum
    float2 acc = make_float2(0.0f, 0.0f);
    #pragma unroll 4
    for (int c = 0; c < CTX; c++) {
        float  p = logits[h][c];
        float2 v = *reinterpret_cast<const float2*>(vp[c] + off);
        acc.x += p * v.x;
        acc.y += p * v.y;
    }
    acc.x = rn_tf32(acc.x);
    acc.y = rn_tf32(acc.y);
    *reinterpret_cast<float2*>(outb + (size_t)bl * DD + off) = acc;
}

// ---------------------------------------------------------------------------
extern "C" void kernel_launch(void* const* d_in, const int* in_sizes, int n_in,
                              void* d_out, int out_size)
{
    const float* spatial = (const float*)d_in[0];
    const int*   topk    = (const int*)  d_in[1];
    const float* dist    = (const float*)d_in[2];
    const float* glat    = (const float*)d_in[3];
    const float* Wq      = (const float*)d_in[4];
    const float* Wk      = (const float*)d_in[5];
    const float* Wv      = (const float*)d_in[6];
    const float* Wo      = (const float*)d_in[7];
    const float* bo      = (const float*)d_in[8];
    const float* lsig    = (const float*)d_in[9];
    const float* gbias   = (const float*)d_in[10];
    float* out = (float*)d_out;

    float *Qp, *Kp, *Vp, *Ap, *Kgp, *Vgp;
    float *spc, *glc, *wqc, *wkc, *wvc, *woc;
    cudaGetSymbolAddress((void**)&Qp,  g_Q);
    cudaGetSymbolAddress((void**)&Kp,  g_K);
    cudaGetSymbolAddress((void**)&Vp,  g_V);
    cudaGetSymbolAddress((void**)&Ap,  g_attn);
    cudaGetSymbolAddress((void**)&Kgp, g_Kg);
    cudaGetSymbolAddress((void**)&Vgp, g_Vg);
    cudaGetSymbolAddress((void**)&spc, g_sp_cv);
    cudaGetSymbolAddress((void**)&glc, g_gl_cv);
    cudaGetSymbolAddress((void**)&wqc, g_Wq_cv);
    cudaGetSymbolAddress((void**)&wkc, g_Wk_cv);
    cudaGetSymbolAddress((void**)&wvc, g_Wv_cv);
    cudaGetSymbolAddress((void**)&woc, g_Wo_cv);

    cudaFuncSetAttribute(qkv_gemm, cudaFuncAttributeMaxDynamicSharedMemorySize, GEMM_SMEM);
    cudaFuncSetAttribute(out_gemm, cudaFuncAttributeMaxDynamicSharedMemorySize, GEMM_SMEM);

    // Round all GEMM inputs to tf32-representable fp32 (one pass)
    dim3 cvt_grid(64, 6);
    to_tf32_all<<<cvt_grid, 256>>>(
        spatial, spc, BL * DD / 4,
        Wq, wqc, DD * DD / 4,
        Wk, wkc, DD * DD / 4,
        Wv, wvc, DD * DD / 4,
        Wo, woc, DD * DD / 4,
        glat, glc, BB * GG * DD / 4);

    dim3 qkv_grid(4, 33, 3);
    qkv_gemm<<<qkv_grid, 256, GEMM_SMEM>>>(spc, glc, wqc, wkc, wvc,
                                           Qp, Kp, Vp, Kgp, Vgp);

    attn_kernel<<<BL, 256>>>(Qp, Kp, Vp, Kgp, Vgp, topk, dist, lsig, gbias, Ap);

    dim3 out_grid(4, 32);
    out_gemm<<<out_grid, 256, GEMM_SMEM>>>(Ap, woc, bo, out);
}

// round 8
// speedup vs baseline: 1.2394x; 1.0437x over previous
#include <cuda_runtime.h>
#include <cuda_fp16.h>
#include <mma.h>
#include <cstdint>

using namespace nvcuda;

// Problem constants
#define BB   2
#define LL   2048
#define DD   512
#define KK   32
#define GG   32
#define HH   8
#define DHH  64
#define CTX  65        // 1 + K + G
#define BL   (BB*LL)   // 4096

// Scratch buffers (device globals: no allocation allowed)
__device__ float  g_Q   [BL * DD];
__device__ __half g_Kh  [BL * DD];
__device__ __half g_Vh  [BL * DD];
__device__ float  g_attn[BL * DD];
__device__ __half g_Kgh [BB * GG * DD];
__device__ __half g_Vgh [BB * GG * DD];
// tf32-rounded copies of GEMM inputs
__device__ float g_sp_cv[BL * DD];
__device__ float g_gl_cv[BB * GG * DD];
__device__ float g_Wq_cv[DD * DD];
__device__ float g_Wk_cv[DD * DD];
__device__ float g_Wv_cv[DD * DD];
__device__ float g_Wo_cv[DD * DD];

// ---------------------------------------------------------------------------
// tf32 RN rounding helper (cvt.rna.tf32.f32 needs a .b32 destination)
// ---------------------------------------------------------------------------
__device__ __forceinline__ float rn_tf32(float x) {
    uint32_t u;
    asm("cvt.rna.tf32.f32 %0, %1;" : "=r"(u) : "f"(x));
    return __uint_as_float(u);
}

// One kernel converts all 6 input arrays (blockIdx.y selects segment)
__global__ __launch_bounds__(256)
void to_tf32_all(const float* s0, float* d0, int n0,
                 const float* s1, float* d1, int n1,
                 const float* s2, float* d2, int n2,
                 const float* s3, float* d3, int n3,
                 const float* s4, float* d4, int n4,
                 const float* s5, float* d5, int n5)
{
    const float* src; float* dst; int n4cnt;
    switch (blockIdx.y) {
        case 0: src = s0; dst = d0; n4cnt = n0; break;
        case 1: src = s1; dst = d1; n4cnt = n1; break;
        case 2: src = s2; dst = d2; n4cnt = n2; break;
        case 3: src = s3; dst = d3; n4cnt = n3; break;
        case 4: src = s4; dst = d4; n4cnt = n4; break;
        default: src = s5; dst = d5; n4cnt = n5; break;
    }
    int stride = gridDim.x * blockDim.x;
    for (int i = blockIdx.x * blockDim.x + threadIdx.x; i < n4cnt; i += stride) {
        float4 v = reinterpret_cast<const float4*>(src)[i];
        v.x = rn_tf32(v.x); v.y = rn_tf32(v.y);
        v.z = rn_tf32(v.z); v.w = rn_tf32(v.w);
        reinterpret_cast<float4*>(dst)[i] = v;
    }
}

// ---------------------------------------------------------------------------
// cp.async helpers
// ---------------------------------------------------------------------------
__device__ __forceinline__ void cp_async16(void* smem_dst, const void* gsrc) {
    unsigned int sa = (unsigned int)__cvta_generic_to_shared(smem_dst);
    asm volatile("cp.async.cg.shared.global [%0], [%1], 16;\n" :: "r"(sa), "l"(gsrc));
}
__device__ __forceinline__ void cp_commit() {
    asm volatile("cp.async.commit_group;\n" ::);
}
template <int N>
__device__ __forceinline__ void cp_wait() {
    asm volatile("cp.async.wait_group %0;\n" :: "n"(N));
}

// ---------------------------------------------------------------------------
// GEMM core: C[0:rows, n0:n0+128] = A[0:rows, 0:512] @ W[512,512] (+bias)
// BM=128, BN=128, BK=32, 3-stage cp.async pipeline, 256 threads.
// Warp grid 4x2, warp tile 32x64 (2x4 wmma tf32 m16n16k8 accumulators).
// Output either fp32 (Cf, optional bias) or fp16 (Ch).
// ---------------------------------------------------------------------------
constexpr int ASTR = 36;    // As row stride (floats)
constexpr int BSTR = 132;   // Bs row stride (floats)
constexpr int STAGE_FLOATS = 128 * ASTR + 32 * BSTR;   // 8832
constexpr int GEMM_SMEM = 3 * STAGE_FLOATS * 4;        // 105984 bytes

__device__ __forceinline__ void issue_stage(
    float* stage, const float* __restrict__ A, const float* __restrict__ W,
    int n0, int k0, int tid, int rmask)
{
    float* As = stage;
    float* Bs = stage + 128 * ASTR;
    #pragma unroll
    for (int t = 0; t < 4; t++) {
        int lin = tid + t * 256;
        int r = lin >> 3, c = (lin & 7) << 2;              // A: 128x32
        cp_async16(&As[r * ASTR + c], &A[(size_t)(r & rmask) * 512 + k0 + c]);
        int rb = lin >> 5, cb = (lin & 31) << 2;           // B: 32x128
        cp_async16(&Bs[rb * BSTR + cb], &W[(size_t)(k0 + rb) * 512 + n0 + cb]);
    }
}

__device__ __forceinline__ void gemm_core(
    const float* __restrict__ A, const float* __restrict__ W,
    float* __restrict__ Cf, __half* __restrict__ Ch,
    const float* __restrict__ bias, int n0, int rows)
{
    extern __shared__ __align__(16) float dsmem[];
    const int tid    = threadIdx.x;
    const int wid    = tid >> 5;
    const int warp_m = wid >> 1;     // 0..3 -> rows warp_m*32
    const int warp_n = wid & 1;      // 0..1 -> cols warp_n*64
    const int rmask  = (rows == 64) ? 63 : 127;

    wmma::fragment<wmma::accumulator, 16, 16, 8, float> acc[2][4];
    #pragma unroll
    for (int i = 0; i < 2; i++)
        #pragma unroll
        for (int j = 0; j < 4; j++)
            wmma::fill_fragment(acc[i][j], 0.0f);

    issue_stage(dsmem,                A, W, n0, 0,  tid, rmask); cp_commit();
    issue_stage(dsmem + STAGE_FLOATS, A, W, n0, 32, tid, rmask); cp_commit();

    for (int it = 0; it < 16; it++) {
        cp_wait<1>();
        __syncthreads();
        if (it + 2 < 16)
            issue_stage(dsmem + ((it + 2) % 3) * STAGE_FLOATS, A, W,
                        n0, (it + 2) * 32, tid, rmask);
        cp_commit();   // commit every iter (possibly empty) to keep counts aligned

        float* As = dsmem + (it % 3) * STAGE_FLOATS;
        float* Bs = As + 128 * ASTR;
        #pragma unroll
        for (int kk = 0; kk < 4; kk++) {
            wmma::fragment<wmma::matrix_a, 16, 16, 8, wmma::precision::tf32,
                           wmma::row_major> af[2];
            wmma::fragment<wmma::matrix_b, 16, 16, 8, wmma::precision::tf32,
                           wmma::row_major> bf[4];
            wmma::load_matrix_sync(af[0], &As[(warp_m * 32     ) * ASTR + kk * 8], ASTR);
            wmma::load_matrix_sync(af[1], &As[(warp_m * 32 + 16) * ASTR + kk * 8], ASTR);
            #pragma unroll
            for (int j = 0; j < 4; j++)
                wmma::load_matrix_sync(bf[j], &Bs[(kk * 8) * BSTR + warp_n * 64 + j * 16], BSTR);
            #pragma unroll
            for (int i = 0; i < 2; i++)
                #pragma unroll
                for (int j = 0; j < 4; j++)
                    wmma::mma_sync(acc[i][j], af[i], bf[j], acc[i][j]);
        }
        __syncthreads();
    }

    if (Ch == nullptr && bias == nullptr) {
        // Direct fp32 store (Q path)
        if (rows == 64 && warp_m >= 2) return;
        #pragma unroll
        for (int i = 0; i < 2; i++)
            #pragma unroll
            for (int j = 0; j < 4; j++)
                wmma::store_matrix_sync(
                    &Cf[(size_t)(warp_m * 32 + i * 16) * 512 + n0 + warp_n * 64 + j * 16],
                    acc[i][j], 512, wmma::mem_row_major);
        return;
    }

    // Stage via smem (reuse pipeline buffer), then convert/bias + store
    float (*Cs)[BSTR] = reinterpret_cast<float(*)[BSTR]>(dsmem);
    #pragma unroll
    for (int i = 0; i < 2; i++)
        #pragma unroll
        for (int j = 0; j < 4; j++)
            wmma::store_matrix_sync(
                &Cs[warp_m * 32 + i * 16][warp_n * 64 + j * 16],
                acc[i][j], BSTR, wmma::mem_row_major);
    __syncthreads();

    const int n4 = rows * 32;           // rows x 128 floats in float4 units
    if (Ch != nullptr) {
        // fp16 output (K/V path)
        for (int lin = tid; lin < n4; lin += 256) {
            int r = lin >> 5, c4 = (lin & 31) << 2;
            float4 v = *reinterpret_cast<const float4*>(&Cs[r][c4]);
            __half2 h0 = __floats2half2_rn(v.x, v.y);
            __half2 h1 = __floats2half2_rn(v.z, v.w);
            __half2* dst = reinterpret_cast<__half2*>(&Ch[(size_t)r * 512 + n0 + c4]);
            dst[0] = h0;
            dst[1] = h1;
        }
    } else {
        // fp32 + bias (output projection)
        for (int lin = tid; lin < n4; lin += 256) {
            int r = lin >> 5, c4 = (lin & 31) << 2;
            float4 v = *reinterpret_cast<const float4*>(&Cs[r][c4]);
            v.x += bias[n0 + c4 + 0];
            v.y += bias[n0 + c4 + 1];
            v.z += bias[n0 + c4 + 2];
            v.w += bias[n0 + c4 + 3];
            *reinterpret_cast<float4*>(&Cf[(size_t)r * 512 + n0 + c4]) = v;
        }
    }
}

// Fused Q/K/V projection (+ global-latent K/V). grid = (4, 33, 3)
__global__ __launch_bounds__(256, 2)
void qkv_gemm(const float* __restrict__ spatial, const float* __restrict__ glat,
              const float* __restrict__ Wq, const float* __restrict__ Wk,
              const float* __restrict__ Wv,
              float* __restrict__ Q, __half* __restrict__ K, __half* __restrict__ V,
              __half* __restrict__ Kg, __half* __restrict__ Vg)
{
    const int z = blockIdx.z, y = blockIdx.y;
    const float* W = (z == 0) ? Wq : (z == 1) ? Wk : Wv;
    if (y < 32) {
        const float* A = spatial + (size_t)y * 128 * 512;
        if (z == 0)
            gemm_core(A, W, Q + (size_t)y * 128 * 512, nullptr, nullptr,
                      blockIdx.x * 128, 128);
        else
            gemm_core(A, W, nullptr,
                      ((z == 1) ? K : V) + (size_t)y * 128 * 512, nullptr,
                      blockIdx.x * 128, 128);
    } else {
        if (z == 0) return;
        gemm_core(glat, W, nullptr, (z == 1) ? Kg : Vg, nullptr,
                  blockIdx.x * 128, 64);
    }
}

// Output projection with bias. grid = (4, 32)
__global__ __launch_bounds__(256, 2)
void out_gemm(const float* __restrict__ A, const float* __restrict__ W,
              const float* __restrict__ bias, float* __restrict__ C)
{
    gemm_core(A + (size_t)blockIdx.y * 128 * 512, W,
              C + (size_t)blockIdx.y * 128 * 512, nullptr, bias,
              blockIdx.x * 128, 128);
}

// ---------------------------------------------------------------------------
// Gather attention: one block per (b,l), one warp per head. K/V in fp16.
// ---------------------------------------------------------------------------
__global__ __launch_bounds__(256)
void attn_kernel(const float*  __restrict__ Q,   const __half* __restrict__ Ksp,
                 const __half* __restrict__ Vsp, const __half* __restrict__ Kg,
                 const __half* __restrict__ Vg,  const int*    __restrict__ topk,
                 const float*  __restrict__ dist,
                 const float*  __restrict__ log_sigma,
                 const float*  __restrict__ gbias_p,
                 float* __restrict__ outb)
{
    const int bl   = blockIdx.x;
    const int b    = bl >> 11;            // L = 2048
    const int tid  = threadIdx.x;
    const int h    = tid >> 5;
    const int lane = tid & 31;

    __shared__ const __half* kp[CTX];
    __shared__ const __half* vp[CTX];
    __shared__ float dist2[33];
    __shared__ float logits[HH][68];

    if (tid < CTX) {
        int c = tid;
        const __half *kq, *vq;
        if (c == 0) {
            kq = Ksp + (size_t)bl * DD;
            vq = Vsp + (size_t)bl * DD;
        } else if (c < 33) {
            int r = b * LL + topk[(size_t)bl * KK + (c - 1)];
            kq = Ksp + (size_t)r * DD;
            vq = Vsp + (size_t)r * DD;
        } else {
            int r = b * GG + (c - 33);
            kq = Kg + (size_t)r * DD;
            vq = Vg + (size_t)r * DD;
        }
        kp[c] = kq;
        vp[c] = vq;
        if (c < 33) {
            float d = (c == 0) ? 0.0f : dist[(size_t)bl * KK + (c - 1)];
            dist2[c] = d * d;
        }
    }
    __syncthreads();

    const float inv2s = 0.5f * __expf(-2.0f * log_sigma[h]);  // 1/(2*sigma^2)
    const float gb    = *gbias_p;
    const float scale = 0.125f;                               // 64^-0.5
    const int   off   = h * DHH + lane * 2;

    const float2 q2 = *reinterpret_cast<const float2*>(Q + (size_t)bl * DD + off);

    // logits
    #pragma unroll 4
    for (int c = 0; c < CTX; c++) {
        float2 kk = __half22float2(*reinterpret_cast<const __half2*>(kp[c] + off));
        float s = q2.x * kk.x + q2.y * kk.y;
        #pragma unroll
        for (int d = 16; d; d >>= 1)
            s += __shfl_xor_sync(0xffffffffu, s, d);
        if (lane == 0)
            logits[h][c] = s * scale + ((c < 33) ? -dist2[c] * inv2s : gb);
    }
    __syncwarp();

    // softmax over 65 entries (per-warp)
    float l0 = logits[h][lane];
    float l1 = logits[h][lane + 32];
    float l2 = (lane == 0) ? logits[h][64] : -1e30f;
    float m = fmaxf(fmaxf(l0, l1), l2);
    #pragma unroll
    for (int d = 16; d; d >>= 1)
        m = fmaxf(m, __shfl_xor_sync(0xffffffffu, m, d));
    float e0 = __expf(l0 - m);
    float e1 = __expf(l1 - m);
    float e2 = (lane == 0) ? __expf(l2 - m) : 0.0f;
    float s = e0 + e1 + e2;
    #pragma unroll
    for (int d = 16; d; d >>= 1)
        s += __shfl_xor_sync(0xffffffffu, s, d);
    float inv = 1.0f / s;
    logits[h][lane]      = e0 * inv;
    logits[h][lane + 32] = e1 * inv;
    if (lane == 0) logits[h][64] = e2 * inv;
    __syncwarp();

    // weighted V sum
    float2 acc = make_float2(0.0f, 0.0f);
    #pragma unroll 4
    for (int c = 0; c < CTX; c++) {
        float  p = logits[h][c];
        float2 v = __half22float2(*reinterpret_cast<const __half2*>(vp[c] + off));
        acc.x += p * v.x;
        acc.y += p * v.y;
    }
    acc.x = rn_tf32(acc.x);
    acc.y = rn_tf32(acc.y);
    *reinterpret_cast<float2*>(outb + (size_t)bl * DD + off) = acc;
}

// ---------------------------------------------------------------------------
extern "C" void kernel_launch(void* const* d_in, const int* in_sizes, int n_in,
                              void* d_out, int out_size)
{
    const float* spatial = (const float*)d_in[0];
    const int*   topk    = (const int*)  d_in[1];
    const float* dist    = (const float*)d_in[2];
    const float* glat    = (const float*)d_in[3];
    const float* Wq      = (const float*)d_in[4];
    const float* Wk      = (const float*)d_in[5];
    const float* Wv      = (const float*)d_in[6];
    const float* Wo      = (const float*)d_in[7];
    const float* bo      = (const float*)d_in[8];
    const float* lsig    = (const float*)d_in[9];
    const float* gbias   = (const float*)d_in[10];
    float* out = (float*)d_out;

    float  *Qp, *Ap;
    __half *Kp, *Vp, *Kgp, *Vgp;
    float  *spc, *glc, *wqc, *wkc, *wvc, *woc;
    cudaGetSymbolAddress((void**)&Qp,  g_Q);
    cudaGetSymbolAddress((void**)&Kp,  g_Kh);
    cudaGetSymbolAddress((void**)&Vp,  g_Vh);
    cudaGetSymbolAddress((void**)&Ap,  g_attn);
    cudaGetSymbolAddress((void**)&Kgp, g_Kgh);
    cudaGetSymbolAddress((void**)&Vgp, g_Vgh);
    cudaGetSymbolAddress((void**)&spc, g_sp_cv);
    cudaGetSymbolAddress((void**)&glc, g_gl_cv);
    cudaGetSymbolAddress((void**)&wqc, g_Wq_cv);
    cudaGetSymbolAddress((void**)&wkc, g_Wk_cv);
    cudaGetSymbolAddress((void**)&wvc, g_Wv_cv);
    cudaGetSymbolAddress((void**)&woc, g_Wo_cv);

    cudaFuncSetAttribute(qkv_gemm, cudaFuncAttributeMaxDynamicSharedMemorySize, GEMM_SMEM);
    cudaFuncSetAttribute(out_gemm, cudaFuncAttributeMaxDynamicSharedMemorySize, GEMM_SMEM);

    // Round all GEMM inputs to tf32-representable fp32 (one pass)
    dim3 cvt_grid(64, 6);
    to_tf32_all<<<cvt_grid, 256>>>(
        spatial, spc, BL * DD / 4,
        Wq, wqc, DD * DD / 4,
        Wk, wkc, DD * DD / 4,
        Wv, wvc, DD * DD / 4,
        Wo, woc, DD * DD / 4,
        glat, glc, BB * GG * DD / 4);

    dim3 qkv_grid(4, 33, 3);
    qkv_gemm<<<qkv_grid, 256, GEMM_SMEM>>>(spc, glc, wqc, wkc, wvc,
                                           Qp, Kp, Vp, Kgp, Vgp);

    attn_kernel<<<BL, 256>>>(Qp, Kp, Vp, Kgp, Vgp, topk, dist, lsig, gbias, Ap);

    dim3 out_grid(4, 32);
    out_gemm<<<out_grid, 256, GEMM_SMEM>>>(Ap, woc, bo, out);
}

// round 9
// speedup vs baseline: 2.0755x; 1.6746x over previous
#include <cuda_runtime.h>
#include <cuda_fp16.h>
#include <mma.h>
#include <cstdint>

using namespace nvcuda;

// Problem constants
#define BB   2
#define LL   2048
#define DD   512
#define KK   32
#define GG   32
#define HH   8
#define DHH  64
#define CTX  65        // 1 + K + G
#define BL   (BB*LL)   // 4096

// Scratch buffers (device globals: no allocation allowed)
__device__ float  g_Q    [BL * DD];          // Q stays fp32 (attn reads it)
__device__ __half g_Kh   [BL * DD];
__device__ __half g_Vh   [BL * DD];
__device__ __half g_attnh[BL * DD];          // attention output (fp16, feeds out_gemm)
__device__ __half g_Kgh  [BB * GG * DD];
__device__ __half g_Vgh  [BB * GG * DD];
// fp16 copies of GEMM inputs
__device__ __half g_sp_h[BL * DD];
__device__ __half g_gl_h[BB * GG * DD];
__device__ __half g_Wq_h[DD * DD];
__device__ __half g_Wk_h[DD * DD];
__device__ __half g_Wv_h[DD * DD];
__device__ __half g_Wo_h[DD * DD];

// ---------------------------------------------------------------------------
// fp32 -> fp16 converter for all 6 GEMM inputs (blockIdx.y selects segment)
// n counts are in float4 (4-element) units.
// ---------------------------------------------------------------------------
__global__ __launch_bounds__(256)
void to_half_all(const float* s0, __half* d0, int n0,
                 const float* s1, __half* d1, int n1,
                 const float* s2, __half* d2, int n2,
                 const float* s3, __half* d3, int n3,
                 const float* s4, __half* d4, int n4,
                 const float* s5, __half* d5, int n5)
{
    const float* src; __half* dst; int n;
    switch (blockIdx.y) {
        case 0: src = s0; dst = d0; n = n0; break;
        case 1: src = s1; dst = d1; n = n1; break;
        case 2: src = s2; dst = d2; n = n2; break;
        case 3: src = s3; dst = d3; n = n3; break;
        case 4: src = s4; dst = d4; n = n4; break;
        default: src = s5; dst = d5; n = n5; break;
    }
    int stride = gridDim.x * blockDim.x;
    for (int i = blockIdx.x * blockDim.x + threadIdx.x; i < n; i += stride) {
        float4 v = reinterpret_cast<const float4*>(src)[i];
        __half2* d2p = reinterpret_cast<__half2*>(dst) + i * 2;
        d2p[0] = __floats2half2_rn(v.x, v.y);
        d2p[1] = __floats2half2_rn(v.z, v.w);
    }
}

// ---------------------------------------------------------------------------
// cp.async helpers
// ---------------------------------------------------------------------------
__device__ __forceinline__ void cp_async16(void* smem_dst, const void* gsrc) {
    unsigned int sa = (unsigned int)__cvta_generic_to_shared(smem_dst);
    asm volatile("cp.async.cg.shared.global [%0], [%1], 16;\n" :: "r"(sa), "l"(gsrc));
}
__device__ __forceinline__ void cp_commit() {
    asm volatile("cp.async.commit_group;\n" ::);
}
template <int N>
__device__ __forceinline__ void cp_wait() {
    asm volatile("cp.async.wait_group %0;\n" :: "n"(N));
}

// ---------------------------------------------------------------------------
// fp16 GEMM core: C[0:rows, n0:n0+128] = A[0:rows, 0:512] @ W[512,512]
// BM=128, BN=128, BK=32, 4-stage cp.async pipeline, 256 threads.
// Warp grid 4x2, warp tile 32x64 (2x4 wmma fp16 m16n16k16, fp32 accum).
// Output: fp32 direct (Q), fp16 (K/V/attn targets), or fp32+bias (final).
// ---------------------------------------------------------------------------
constexpr int ASTR_H = 40;    // As row stride (halves): 32 + 8 pad
constexpr int BSTR_H = 136;   // Bs row stride (halves): 128 + 8 pad
constexpr int STAGE_HALVES = 128 * ASTR_H + 32 * BSTR_H;   // 9472
constexpr int GEMM_SMEM = 4 * STAGE_HALVES * 2;            // 75776 bytes
constexpr int CSTR = 132;     // epilogue float staging stride

__device__ __forceinline__ void issue_stage_h(
    __half* stage, const __half* __restrict__ A, const __half* __restrict__ W,
    int n0, int k0, int tid, int rmask)
{
    __half* As = stage;
    __half* Bs = stage + 128 * ASTR_H;
    #pragma unroll
    for (int t = 0; t < 2; t++) {
        int lin = tid + t * 256;                 // 0..511
        int r  = lin >> 2, c  = (lin & 3) << 3;  // A: 128 rows x 4 chunks(8h)
        cp_async16(&As[r * ASTR_H + c], &A[(size_t)(r & rmask) * 512 + k0 + c]);
        int rb = lin >> 4, cb = (lin & 15) << 3; // B: 32 rows x 16 chunks(8h)
        cp_async16(&Bs[rb * BSTR_H + cb], &W[(size_t)(k0 + rb) * 512 + n0 + cb]);
    }
}

__device__ __forceinline__ void gemm_core_h(
    const __half* __restrict__ A, const __half* __restrict__ W,
    float* __restrict__ Cf, __half* __restrict__ Ch,
    const float* __restrict__ bias, int n0, int rows)
{
    extern __shared__ __align__(16) __half hsmem[];
    const int tid    = threadIdx.x;
    const int wid    = tid >> 5;
    const int warp_m = wid >> 1;     // 0..3 -> rows warp_m*32
    const int warp_n = wid & 1;      // 0..1 -> cols warp_n*64
    const int rmask  = (rows == 64) ? 63 : 127;

    wmma::fragment<wmma::accumulator, 16, 16, 16, float> acc[2][4];
    #pragma unroll
    for (int i = 0; i < 2; i++)
        #pragma unroll
        for (int j = 0; j < 4; j++)
            wmma::fill_fragment(acc[i][j], 0.0f);

    // Preload 3 of 4 stages
    #pragma unroll
    for (int s = 0; s < 3; s++) {
        issue_stage_h(hsmem + s * STAGE_HALVES, A, W, n0, s * 32, tid, rmask);
        cp_commit();
    }

    for (int it = 0; it < 16; it++) {
        cp_wait<2>();          // stage `it` resident, 2 stages still in flight
        __syncthreads();       // also guards buffer (it+3)&3 = (it-1)&3 reuse
        if (it + 3 < 16)
            issue_stage_h(hsmem + ((it + 3) & 3) * STAGE_HALVES, A, W,
                          n0, (it + 3) * 32, tid, rmask);
        cp_commit();           // one group per iter keeps counts aligned

        __half* As = hsmem + (it & 3) * STAGE_HALVES;
        __half* Bs = As + 128 * ASTR_H;
        #pragma unroll
        for (int ks = 0; ks < 2; ks++) {
            wmma::fragment<wmma::matrix_a, 16, 16, 16, half, wmma::row_major> af[2];
            wmma::fragment<wmma::matrix_b, 16, 16, 16, half, wmma::row_major> bf[4];
            wmma::load_matrix_sync(af[0], &As[(warp_m * 32     ) * ASTR_H + ks * 16], ASTR_H);
            wmma::load_matrix_sync(af[1], &As[(warp_m * 32 + 16) * ASTR_H + ks * 16], ASTR_H);
            #pragma unroll
            for (int j = 0; j < 4; j++)
                wmma::load_matrix_sync(bf[j], &Bs[(ks * 16) * BSTR_H + warp_n * 64 + j * 16], BSTR_H);
            #pragma unroll
            for (int i = 0; i < 2; i++)
                #pragma unroll
                for (int j = 0; j < 4; j++)
                    wmma::mma_sync(acc[i][j], af[i], bf[j], acc[i][j]);
        }
    }
    __syncthreads();   // all compute done before epilogue smem reuse

    if (Ch == nullptr && bias == nullptr) {
        // Direct fp32 store (Q path)
        #pragma unroll
        for (int i = 0; i < 2; i++)
            #pragma unroll
            for (int j = 0; j < 4; j++)
                wmma::store_matrix_sync(
                    &Cf[(size_t)(warp_m * 32 + i * 16) * 512 + n0 + warp_n * 64 + j * 16],
                    acc[i][j], 512, wmma::mem_row_major);
        return;
    }

    // Stage via smem (reuse pipeline buffer as float[128][CSTR])
    float (*Cs)[CSTR] = reinterpret_cast<float(*)[CSTR]>(hsmem);
    #pragma unroll
    for (int i = 0; i < 2; i++)
        #pragma unroll
        for (int j = 0; j < 4; j++)
            wmma::store_matrix_sync(
                &Cs[warp_m * 32 + i * 16][warp_n * 64 + j * 16],
                acc[i][j], CSTR, wmma::mem_row_major);
    __syncthreads();

    const int n4 = rows * 32;              // rows x 128 floats in float4 units
    if (Ch != nullptr) {
        for (int lin = tid; lin < n4; lin += 256) {
            int r = lin >> 5, c4 = (lin & 31) << 2;
            float4 v = *reinterpret_cast<const float4*>(&Cs[r][c4]);
            __half2* dst = reinterpret_cast<__half2*>(&Ch[(size_t)r * 512 + n0 + c4]);
            dst[0] = __floats2half2_rn(v.x, v.y);
            dst[1] = __floats2half2_rn(v.z, v.w);
        }
    } else {
        for (int lin = tid; lin < n4; lin += 256) {
            int r = lin >> 5, c4 = (lin & 31) << 2;
            float4 v = *reinterpret_cast<const float4*>(&Cs[r][c4]);
            v.x += bias[n0 + c4 + 0];
            v.y += bias[n0 + c4 + 1];
            v.z += bias[n0 + c4 + 2];
            v.w += bias[n0 + c4 + 3];
            *reinterpret_cast<float4*>(&Cf[(size_t)r * 512 + n0 + c4]) = v;
        }
    }
}

// Fused Q/K/V projection (+ global-latent K/V). grid = (4, 33, 3)
__global__ __launch_bounds__(256, 2)
void qkv_gemm(const __half* __restrict__ spatial, const __half* __restrict__ glat,
              const __half* __restrict__ Wq, const __half* __restrict__ Wk,
              const __half* __restrict__ Wv,
              float* __restrict__ Q, __half* __restrict__ K, __half* __restrict__ V,
              __half* __restrict__ Kg, __half* __restrict__ Vg)
{
    const int z = blockIdx.z, y = blockIdx.y;
    const __half* W = (z == 0) ? Wq : (z == 1) ? Wk : Wv;
    if (y < 32) {
        const __half* A = spatial + (size_t)y * 128 * 512;
        if (z == 0)
            gemm_core_h(A, W, Q + (size_t)y * 128 * 512, nullptr, nullptr,
                        blockIdx.x * 128, 128);
        else
            gemm_core_h(A, W, nullptr,
                        ((z == 1) ? K : V) + (size_t)y * 128 * 512, nullptr,
                        blockIdx.x * 128, 128);
    } else {
        if (z == 0) return;
        gemm_core_h(glat, W, nullptr, (z == 1) ? Kg : Vg, nullptr,
                    blockIdx.x * 128, 64);
    }
}

// Output projection with bias. grid = (4, 32)
__global__ __launch_bounds__(256, 2)
void out_gemm(const __half* __restrict__ A, const __half* __restrict__ W,
              const float* __restrict__ bias, float* __restrict__ C)
{
    gemm_core_h(A + (size_t)blockIdx.y * 128 * 512, W,
                C + (size_t)blockIdx.y * 128 * 512, nullptr, bias,
                blockIdx.x * 128, 128);
}

// ---------------------------------------------------------------------------
// Gather attention: one block per (b,l), one warp per head. K/V fp16,
// output written as fp16 (consumed by out_gemm).
// ---------------------------------------------------------------------------
__global__ __launch_bounds__(256)
void attn_kernel(const float*  __restrict__ Q,   const __half* __restrict__ Ksp,
                 const __half* __restrict__ Vsp, const __half* __restrict__ Kg,
                 const __half* __restrict__ Vg,  const int*    __restrict__ topk,
                 const float*  __restrict__ dist,
                 const float*  __restrict__ log_sigma,
                 const float*  __restrict__ gbias_p,
                 __half* __restrict__ outh)
{
    const int bl   = blockIdx.x;
    const int b    = bl >> 11;            // L = 2048
    const int tid  = threadIdx.x;
    const int h    = tid >> 5;
    const int lane = tid & 31;

    __shared__ const __half* kp[CTX];
    __shared__ const __half* vp[CTX];
    __shared__ float dist2[33];
    __shared__ float logits[HH][68];

    if (tid < CTX) {
        int c = tid;
        const __half *kq, *vq;
        if (c == 0) {
            kq = Ksp + (size_t)bl * DD;
            vq = Vsp + (size_t)bl * DD;
        } else if (c < 33) {
            int r = b * LL + topk[(size_t)bl * KK + (c - 1)];
            kq = Ksp + (size_t)r * DD;
            vq = Vsp + (size_t)r * DD;
        } else {
            int r = b * GG + (c - 33);
            kq = Kg + (size_t)r * DD;
            vq = Vg + (size_t)r * DD;
        }
        kp[c] = kq;
        vp[c] = vq;
        if (c < 33) {
            float d = (c == 0) ? 0.0f : dist[(size_t)bl * KK + (c - 1)];
            dist2[c] = d * d;
        }
    }
    __syncthreads();

    const float inv2s = 0.5f * __expf(-2.0f * log_sigma[h]);  // 1/(2*sigma^2)
    const float gb    = *gbias_p;
    const float scale = 0.125f;                               // 64^-0.5
    const int   off   = h * DHH + lane * 2;

    const float2 q2 = *reinterpret_cast<const float2*>(Q + (size_t)bl * DD + off);

    // logits
    #pragma unroll 4
    for (int c = 0; c < CTX; c++) {
        float2 kk = __half22float2(*reinterpret_cast<const __half2*>(kp[c] + off));
        float s = q2.x * kk.x + q2.y * kk.y;
        #pragma unroll
        for (int d = 16; d; d >>= 1)
            s += __shfl_xor_sync(0xffffffffu, s, d);
        if (lane == 0)
            logits[h][c] = s * scale + ((c < 33) ? -dist2[c] * inv2s : gb);
    }
    __syncwarp();

    // softmax over 65 entries (per-warp)
    float l0 = logits[h][lane];
    float l1 = logits[h][lane + 32];
    float l2 = (lane == 0) ? logits[h][64] : -1e30f;
    float m = fmaxf(fmaxf(l0, l1), l2);
    #pragma unroll
    for (int d = 16; d; d >>= 1)
        m = fmaxf(m, __shfl_xor_sync(0xffffffffu, m, d));
    float e0 = __expf(l0 - m);
    float e1 = __expf(l1 - m);
    float e2 = (lane == 0) ? __expf(l2 - m) : 0.0f;
    float s = e0 + e1 + e2;
    #pragma unroll
    for (int d = 16; d; d >>= 1)
        s += __shfl_xor_sync(0xffffffffu, s, d);
    float inv = 1.0f / s;
    logits[h][lane]      = e0 * inv;
    logits[h][lane + 32] = e1 * inv;
    if (lane == 0) logits[h][64] = e2 * inv;
    __syncwarp();

    // weighted V sum
    float2 acc = make_float2(0.0f, 0.0f);
    #pragma unroll 4
    for (int c = 0; c < CTX; c++) {
        float  p = logits[h][c];
        float2 v = __half22float2(*reinterpret_cast<const __half2*>(vp[c] + off));
        acc.x += p * v.x;
        acc.y += p * v.y;
    }
    *reinterpret_cast<__half2*>(outh + (size_t)bl * DD + off) =
        __floats2half2_rn(acc.x, acc.y);
}

// ---------------------------------------------------------------------------
extern "C" void kernel_launch(void* const* d_in, const int* in_sizes, int n_in,
                              void* d_out, int out_size)
{
    const float* spatial = (const float*)d_in[0];
    const int*   topk    = (const int*)  d_in[1];
    const float* dist    = (const float*)d_in[2];
    const float* glat    = (const float*)d_in[3];
    const float* Wq      = (const float*)d_in[4];
    const float* Wk      = (const float*)d_in[5];
    const float* Wv      = (const float*)d_in[6];
    const float* Wo      = (const float*)d_in[7];
    const float* bo      = (const float*)d_in[8];
    const float* lsig    = (const float*)d_in[9];
    const float* gbias   = (const float*)d_in[10];
    float* out = (float*)d_out;

    float  *Qp;
    __half *Kp, *Vp, *Ah, *Kgp, *Vgp;
    __half *sph, *glh, *wqh, *wkh, *wvh, *woh;
    cudaGetSymbolAddress((void**)&Qp,  g_Q);
    cudaGetSymbolAddress((void**)&Kp,  g_Kh);
    cudaGetSymbolAddress((void**)&Vp,  g_Vh);
    cudaGetSymbolAddress((void**)&Ah,  g_attnh);
    cudaGetSymbolAddress((void**)&Kgp, g_Kgh);
    cudaGetSymbolAddress((void**)&Vgp, g_Vgh);
    cudaGetSymbolAddress((void**)&sph, g_sp_h);
    cudaGetSymbolAddress((void**)&glh, g_gl_h);
    cudaGetSymbolAddress((void**)&wqh, g_Wq_h);
    cudaGetSymbolAddress((void**)&wkh, g_Wk_h);
    cudaGetSymbolAddress((void**)&wvh, g_Wv_h);
    cudaGetSymbolAddress((void**)&woh, g_Wo_h);

    cudaFuncSetAttribute(qkv_gemm, cudaFuncAttributeMaxDynamicSharedMemorySize, GEMM_SMEM);
    cudaFuncSetAttribute(out_gemm, cudaFuncAttributeMaxDynamicSharedMemorySize, GEMM_SMEM);

    // Convert all GEMM inputs to fp16 (one pass)
    dim3 cvt_grid(64, 6);
    to_half_all<<<cvt_grid, 256>>>(
        spatial, sph, BL * DD / 4,
        Wq, wqh, DD * DD / 4,
        Wk, wkh, DD * DD / 4,
        Wv, wvh, DD * DD / 4,
        Wo, woh, DD * DD / 4,
        glat, glh, BB * GG * DD / 4);

    dim3 qkv_grid(4, 33, 3);
    qkv_gemm<<<qkv_grid, 256, GEMM_SMEM>>>(sph, glh, wqh, wkh, wvh,
                                           Qp, Kp, Vp, Kgp, Vgp);

    attn_kernel<<<BL, 256>>>(Qp, Kp, Vp, Kgp, Vgp, topk, dist, lsig, gbias, Ah);

    dim3 out_grid(4, 32);
    out_gemm<<<out_grid, 256, GEMM_SMEM>>>(Ah, woh, bo, out);
}

// round 10
// speedup vs baseline: 2.1325x; 1.0275x over previous
#include <cuda_runtime.h>
#include <cuda_fp16.h>
#include <mma.h>
#include <cstdint>

using namespace nvcuda;

// Problem constants
#define BB   2
#define LL   2048
#define DD   512
#define KK   32
#define GG   32
#define HH   8
#define DHH  64
#define CTX  65        // 1 + K + G
#define BL   (BB*LL)   // 4096

// Scratch buffers (device globals: no allocation allowed)
__device__ __half g_Qh   [BL * DD];
__device__ __half g_Kh   [BL * DD];
__device__ __half g_Vh   [BL * DD];
__device__ __half g_attnh[BL * DD];          // attention output (fp16)
__device__ __half g_Kgh  [BB * GG * DD];
__device__ __half g_Vgh  [BB * GG * DD];
// fp16 copies of GEMM inputs
__device__ __half g_sp_h[BL * DD];
__device__ __half g_gl_h[BB * GG * DD];
__device__ __half g_Wq_h[DD * DD];
__device__ __half g_Wk_h[DD * DD];
__device__ __half g_Wv_h[DD * DD];
__device__ __half g_Wo_h[DD * DD];

// ---------------------------------------------------------------------------
// fp32 -> fp16 converter for all 6 GEMM inputs (blockIdx.y selects segment)
// n counts are in float4 (4-element) units.
// ---------------------------------------------------------------------------
__global__ __launch_bounds__(256)
void to_half_all(const float* s0, __half* d0, int n0,
                 const float* s1, __half* d1, int n1,
                 const float* s2, __half* d2, int n2,
                 const float* s3, __half* d3, int n3,
                 const float* s4, __half* d4, int n4,
                 const float* s5, __half* d5, int n5)
{
    const float* src; __half* dst; int n;
    switch (blockIdx.y) {
        case 0: src = s0; dst = d0; n = n0; break;
        case 1: src = s1; dst = d1; n = n1; break;
        case 2: src = s2; dst = d2; n = n2; break;
        case 3: src = s3; dst = d3; n = n3; break;
        case 4: src = s4; dst = d4; n = n4; break;
        default: src = s5; dst = d5; n = n5; break;
    }
    int stride = gridDim.x * blockDim.x;
    for (int i = blockIdx.x * blockDim.x + threadIdx.x; i < n; i += stride) {
        float4 v = reinterpret_cast<const float4*>(src)[i];
        __half2* d2p = reinterpret_cast<__half2*>(dst) + i * 2;
        d2p[0] = __floats2half2_rn(v.x, v.y);
        d2p[1] = __floats2half2_rn(v.z, v.w);
    }
}

// ---------------------------------------------------------------------------
// cp.async helpers
// ---------------------------------------------------------------------------
__device__ __forceinline__ void cp_async16(void* smem_dst, const void* gsrc) {
    unsigned int sa = (unsigned int)__cvta_generic_to_shared(smem_dst);
    asm volatile("cp.async.cg.shared.global [%0], [%1], 16;\n" :: "r"(sa), "l"(gsrc));
}
__device__ __forceinline__ void cp_commit() {
    asm volatile("cp.async.commit_group;\n" ::);
}
template <int N>
__device__ __forceinline__ void cp_wait() {
    asm volatile("cp.async.wait_group %0;\n" :: "n"(N));
}

// ---------------------------------------------------------------------------
// fp16 GEMM core: C[0:rows, n0:n0+128] = A[0:rows, 0:512] @ W[512,512]
// BM=128, BN=128, BK=64 per iteration, 3-stage cp.async pipeline, 256 threads.
// Warp grid 4x2, warp tile 32x64 (2x4 wmma fp16 m16n16k16, fp32 accum).
// 8 mainloop iterations, ONE syncthreads per iteration.
// ---------------------------------------------------------------------------
constexpr int ASTR_H = 72;    // As row stride (halves): 64 + 8 pad
constexpr int BSTR_H = 136;   // Bs row stride (halves): 128 + 8 pad
constexpr int STAGE_HALVES = 128 * ASTR_H + 64 * BSTR_H;   // 17920
constexpr int GEMM_SMEM = 3 * STAGE_HALVES * 2;            // 107520 bytes
constexpr int CSTR = 132;     // epilogue float staging stride

__device__ __forceinline__ void issue_stage_h(
    __half* stage, const __half* __restrict__ A, const __half* __restrict__ W,
    int n0, int k0, int tid, int rmask)
{
    __half* As = stage;
    __half* Bs = stage + 128 * ASTR_H;
    #pragma unroll
    for (int t = 0; t < 4; t++) {
        int lin = tid + t * 256;                 // 0..1023
        int r  = lin >> 3, c  = (lin & 7) << 3;  // A: 128 rows x 8 chunks(8h)
        cp_async16(&As[r * ASTR_H + c], &A[(size_t)(r & rmask) * 512 + k0 + c]);
        int rb = lin >> 4, cb = (lin & 15) << 3; // B: 64 rows x 16 chunks(8h)
        cp_async16(&Bs[rb * BSTR_H + cb], &W[(size_t)(k0 + rb) * 512 + n0 + cb]);
    }
}

__device__ __forceinline__ void gemm_core_h(
    const __half* __restrict__ A, const __half* __restrict__ W,
    float* __restrict__ Cf, __half* __restrict__ Ch,
    const float* __restrict__ bias, int n0, int rows)
{
    extern __shared__ __align__(16) __half hsmem[];
    const int tid    = threadIdx.x;
    const int wid    = tid >> 5;
    const int warp_m = wid >> 1;     // 0..3 -> rows warp_m*32
    const int warp_n = wid & 1;      // 0..1 -> cols warp_n*64
    const int rmask  = (rows == 64) ? 63 : 127;

    wmma::fragment<wmma::accumulator, 16, 16, 16, float> acc[2][4];
    #pragma unroll
    for (int i = 0; i < 2; i++)
        #pragma unroll
        for (int j = 0; j < 4; j++)
            wmma::fill_fragment(acc[i][j], 0.0f);

    // Preload 2 of 3 stages (BK=64 each)
    #pragma unroll
    for (int s = 0; s < 2; s++) {
        issue_stage_h(hsmem + s * STAGE_HALVES, A, W, n0, s * 64, tid, rmask);
        cp_commit();
    }

    for (int it = 0; it < 8; it++) {
        cp_wait<1>();          // stage `it` resident
        __syncthreads();       // also guards buffer (it+2)%3 reuse
        if (it + 2 < 8)
            issue_stage_h(hsmem + ((it + 2) % 3) * STAGE_HALVES, A, W,
                          n0, (it + 2) * 64, tid, rmask);
        cp_commit();           // one group per iter keeps counts aligned

        __half* As = hsmem + (it % 3) * STAGE_HALVES;
        __half* Bs = As + 128 * ASTR_H;
        #pragma unroll
        for (int ks = 0; ks < 4; ks++) {
            wmma::fragment<wmma::matrix_a, 16, 16, 16, half, wmma::row_major> af[2];
            wmma::fragment<wmma::matrix_b, 16, 16, 16, half, wmma::row_major> bf[4];
            wmma::load_matrix_sync(af[0], &As[(warp_m * 32     ) * ASTR_H + ks * 16], ASTR_H);
            wmma::load_matrix_sync(af[1], &As[(warp_m * 32 + 16) * ASTR_H + ks * 16], ASTR_H);
            #pragma unroll
            for (int j = 0; j < 4; j++)
                wmma::load_matrix_sync(bf[j], &Bs[(ks * 16) * BSTR_H + warp_n * 64 + j * 16], BSTR_H);
            #pragma unroll
            for (int i = 0; i < 2; i++)
                #pragma unroll
                for (int j = 0; j < 4; j++)
                    wmma::mma_sync(acc[i][j], af[i], bf[j], acc[i][j]);
        }
    }
    __syncthreads();   // all compute done before epilogue smem reuse

    // Stage via smem (reuse pipeline buffer as float[128][CSTR])
    float (*Cs)[CSTR] = reinterpret_cast<float(*)[CSTR]>(hsmem);
    #pragma unroll
    for (int i = 0; i < 2; i++)
        #pragma unroll
        for (int j = 0; j < 4; j++)
            wmma::store_matrix_sync(
                &Cs[warp_m * 32 + i * 16][warp_n * 64 + j * 16],
                acc[i][j], CSTR, wmma::mem_row_major);
    __syncthreads();

    const int n4 = rows * 32;              // rows x 128 floats in float4 units
    if (Ch != nullptr) {
        for (int lin = tid; lin < n4; lin += 256) {
            int r = lin >> 5, c4 = (lin & 31) << 2;
            float4 v = *reinterpret_cast<const float4*>(&Cs[r][c4]);
            __half2* dst = reinterpret_cast<__half2*>(&Ch[(size_t)r * 512 + n0 + c4]);
            dst[0] = __floats2half2_rn(v.x, v.y);
            dst[1] = __floats2half2_rn(v.z, v.w);
        }
    } else {
        for (int lin = tid; lin < n4; lin += 256) {
            int r = lin >> 5, c4 = (lin & 31) << 2;
            float4 v = *reinterpret_cast<const float4*>(&Cs[r][c4]);
            v.x += bias[n0 + c4 + 0];
            v.y += bias[n0 + c4 + 1];
            v.z += bias[n0 + c4 + 2];
            v.w += bias[n0 + c4 + 3];
            *reinterpret_cast<float4*>(&Cf[(size_t)r * 512 + n0 + c4]) = v;
        }
    }
}

// Fused Q/K/V projection (+ global-latent K/V). grid = (4, 33, 3)
__global__ __launch_bounds__(256, 2)
void qkv_gemm(const __half* __restrict__ spatial, const __half* __restrict__ glat,
              const __half* __restrict__ Wq, const __half* __restrict__ Wk,
              const __half* __restrict__ Wv,
              __half* __restrict__ Q, __half* __restrict__ K, __half* __restrict__ V,
              __half* __restrict__ Kg, __half* __restrict__ Vg)
{
    const int z = blockIdx.z, y = blockIdx.y;
    const __half* W = (z == 0) ? Wq : (z == 1) ? Wk : Wv;
    if (y < 32) {
        const __half* A = spatial + (size_t)y * 128 * 512;
        __half* C = ((z == 0) ? Q : (z == 1) ? K : V) + (size_t)y * 128 * 512;
        gemm_core_h(A, W, nullptr, C, nullptr, blockIdx.x * 128, 128);
    } else {
        if (z == 0) return;
        gemm_core_h(glat, W, nullptr, (z == 1) ? Kg : Vg, nullptr,
                    blockIdx.x * 128, 64);
    }
}

// Output projection with bias. grid = (4, 32)
__global__ __launch_bounds__(256, 2)
void out_gemm(const __half* __restrict__ A, const __half* __restrict__ W,
              const float* __restrict__ bias, float* __restrict__ C)
{
    gemm_core_h(A + (size_t)blockIdx.y * 128 * 512, W,
                C + (size_t)blockIdx.y * 128 * 512, nullptr, bias,
                blockIdx.x * 128, 128);
}

// ---------------------------------------------------------------------------
// Gather attention: one block per (b,l), one warp per head. Q/K/V fp16,
// output written as fp16 (consumed by out_gemm).
// ---------------------------------------------------------------------------
__global__ __launch_bounds__(256)
void attn_kernel(const __half* __restrict__ Q,   const __half* __restrict__ Ksp,
                 const __half* __restrict__ Vsp, const __half* __restrict__ Kg,
                 const __half* __restrict__ Vg,  const int*    __restrict__ topk,
                 const float*  __restrict__ dist,
                 const float*  __restrict__ log_sigma,
                 const float*  __restrict__ gbias_p,
                 __half* __restrict__ outh)
{
    const int bl   = blockIdx.x;
    const int b    = bl >> 11;            // L = 2048
    const int tid  = threadIdx.x;
    const int h    = tid >> 5;
    const int lane = tid & 31;

    __shared__ const __half* kp[CTX];
    __shared__ const __half* vp[CTX];
    __shared__ float dist2[33];
    __shared__ float logits[HH][68];

    if (tid < CTX) {
        int c = tid;
        const __half *kq, *vq;
        if (c == 0) {
            kq = Ksp + (size_t)bl * DD;
            vq = Vsp + (size_t)bl * DD;
        } else if (c < 33) {
            int r = b * LL + topk[(size_t)bl * KK + (c - 1)];
            kq = Ksp + (size_t)r * DD;
            vq = Vsp + (size_t)r * DD;
        } else {
            int r = b * GG + (c - 33);
            kq = Kg + (size_t)r * DD;
            vq = Vg + (size_t)r * DD;
        }
        kp[c] = kq;
        vp[c] = vq;
        if (c < 33) {
            float d = (c == 0) ? 0.0f : dist[(size_t)bl * KK + (c - 1)];
            dist2[c] = d * d;
        }
    }
    __syncthreads();

    const float inv2s = 0.5f * __expf(-2.0f * log_sigma[h]);  // 1/(2*sigma^2)
    const float gb    = *gbias_p;
    const float scale = 0.125f;                               // 64^-0.5
    const int   off   = h * DHH + lane * 2;

    const float2 q2 =
        __half22float2(*reinterpret_cast<const __half2*>(Q + (size_t)bl * DD + off));

    // logits
    #pragma unroll 8
    for (int c = 0; c < CTX; c++) {
        float2 kk = __half22float2(*reinterpret_cast<const __half2*>(kp[c] + off));
        float s = q2.x * kk.x + q2.y * kk.y;
        #pragma unroll
        for (int d = 16; d; d >>= 1)
            s += __shfl_xor_sync(0xffffffffu, s, d);
        if (lane == 0)
            logits[h][c] = s * scale + ((c < 33) ? -dist2[c] * inv2s : gb);
    }
    __syncwarp();

    // softmax over 65 entries (per-warp)
    float l0 = logits[h][lane];
    float l1 = logits[h][lane + 32];
    float l2 = (lane == 0) ? logits[h][64] : -1e30f;
    float m = fmaxf(fmaxf(l0, l1), l2);
    #pragma unroll
    for (int d = 16; d; d >>= 1)
        m = fmaxf(m, __shfl_xor_sync(0xffffffffu, m, d));
    float e0 = __expf(l0 - m);
    float e1 = __expf(l1 - m);
    float e2 = (lane == 0) ? __expf(l2 - m) : 0.0f;
    float s = e0 + e1 + e2;
    #pragma unroll
    for (int d = 16; d; d >>= 1)
        s += __shfl_xor_sync(0xffffffffu, s, d);
    float inv = 1.0f / s;
    logits[h][lane]      = e0 * inv;
    logits[h][lane + 32] = e1 * inv;
    if (lane == 0) logits[h][64] = e2 * inv;
    __syncwarp();

    // weighted V sum
    float2 acc = make_float2(0.0f, 0.0f);
    #pragma unroll 8
    for (int c = 0; c < CTX; c++) {
        float  p = logits[h][c];
        float2 v = __half22float2(*reinterpret_cast<const __half2*>(vp[c] + off));
        acc.x += p * v.x;
        acc.y += p * v.y;
    }
    *reinterpret_cast<__half2*>(outh + (size_t)bl * DD + off) =
        __floats2half2_rn(acc.x, acc.y);
}

// ---------------------------------------------------------------------------
extern "C" void kernel_launch(void* const* d_in, const int* in_sizes, int n_in,
                              void* d_out, int out_size)
{
    const float* spatial = (const float*)d_in[0];
    const int*   topk    = (const int*)  d_in[1];
    const float* dist    = (const float*)d_in[2];
    const float* glat    = (const float*)d_in[3];
    const float* Wq      = (const float*)d_in[4];
    const float* Wk      = (const float*)d_in[5];
    const float* Wv      = (const float*)d_in[6];
    const float* Wo      = (const float*)d_in[7];
    const float* bo      = (const float*)d_in[8];
    const float* lsig    = (const float*)d_in[9];
    const float* gbias   = (const float*)d_in[10];
    float* out = (float*)d_out;

    __half *Qp, *Kp, *Vp, *Ah, *Kgp, *Vgp;
    __half *sph, *glh, *wqh, *wkh, *wvh, *woh;
    cudaGetSymbolAddress((void**)&Qp,  g_Qh);
    cudaGetSymbolAddress((void**)&Kp,  g_Kh);
    cudaGetSymbolAddress((void**)&Vp,  g_Vh);
    cudaGetSymbolAddress((void**)&Ah,  g_attnh);
    cudaGetSymbolAddress((void**)&Kgp, g_Kgh);
    cudaGetSymbolAddress((void**)&Vgp, g_Vgh);
    cudaGetSymbolAddress((void**)&sph, g_sp_h);
    cudaGetSymbolAddress((void**)&glh, g_gl_h);
    cudaGetSymbolAddress((void**)&wqh, g_Wq_h);
    cudaGetSymbolAddress((void**)&wkh, g_Wk_h);
    cudaGetSymbolAddress((void**)&wvh, g_Wv_h);
    cudaGetSymbolAddress((void**)&woh, g_Wo_h);

    cudaFuncSetAttribute(qkv_gemm, cudaFuncAttributeMaxDynamicSharedMemorySize, GEMM_SMEM);
    cudaFuncSetAttribute(out_gemm, cudaFuncAttributeMaxDynamicSharedMemorySize, GEMM_SMEM);

    // Convert all GEMM inputs to fp16 (one pass)
    dim3 cvt_grid(64, 6);
    to_half_all<<<cvt_grid, 256>>>(
        spatial, sph, BL * DD / 4,
        Wq, wqh, DD * DD / 4,
        Wk, wkh, DD * DD / 4,
        Wv, wvh, DD * DD / 4,
        Wo, woh, DD * DD / 4,
        glat, glh, BB * GG * DD / 4);

    dim3 qkv_grid(4, 33, 3);
    qkv_gemm<<<qkv_grid, 256, GEMM_SMEM>>>(sph, glh, wqh, wkh, wvh,
                                           Qp, Kp, Vp, Kgp, Vgp);

    attn_kernel<<<BL, 256>>>(Qp, Kp, Vp, Kgp, Vgp, topk, dist, lsig, gbias, Ah);

    dim3 out_grid(4, 32);
    out_gemm<<<out_grid, 256, GEMM_SMEM>>>(Ah, woh, bo, out);
}

// round 11
// speedup vs baseline: 3.3000x; 1.5475x over previous
#include <cuda_runtime.h>
#include <cuda_fp16.h>
#include <mma.h>
#include <cstdint>

using namespace nvcuda;

// Problem constants
#define BB   2
#define LL   2048
#define DD   512
#define KK   32
#define GG   32
#define HH   8
#define DHH  64
#define CTX  65        // 1 + K + G
#define BL   (BB*LL)   // 4096

// Scratch buffers (device globals: no allocation allowed)
__device__ __half g_Qh   [BL * DD];
__device__ __half g_Kh   [BL * DD];
__device__ __half g_Vh   [BL * DD];
__device__ __half g_attnh[BL * DD];          // attention output (fp16)
__device__ __half g_Kgh  [BB * GG * DD];
__device__ __half g_Vgh  [BB * GG * DD];
// fp16 copies of GEMM inputs
__device__ __half g_sp_h[BL * DD];
__device__ __half g_gl_h[BB * GG * DD];
__device__ __half g_Wq_h[DD * DD];
__device__ __half g_Wk_h[DD * DD];
__device__ __half g_Wv_h[DD * DD];
__device__ __half g_Wo_h[DD * DD];

// ---------------------------------------------------------------------------
// fp32 -> fp16 converter for all 6 GEMM inputs (blockIdx.y selects segment)
// n counts are in float4 (4-element) units.
// ---------------------------------------------------------------------------
__global__ __launch_bounds__(256)
void to_half_all(const float* s0, __half* d0, int n0,
                 const float* s1, __half* d1, int n1,
                 const float* s2, __half* d2, int n2,
                 const float* s3, __half* d3, int n3,
                 const float* s4, __half* d4, int n4,
                 const float* s5, __half* d5, int n5)
{
    const float* src; __half* dst; int n;
    switch (blockIdx.y) {
        case 0: src = s0; dst = d0; n = n0; break;
        case 1: src = s1; dst = d1; n = n1; break;
        case 2: src = s2; dst = d2; n = n2; break;
        case 3: src = s3; dst = d3; n = n3; break;
        case 4: src = s4; dst = d4; n = n4; break;
        default: src = s5; dst = d5; n = n5; break;
    }
    int stride = gridDim.x * blockDim.x;
    for (int i = blockIdx.x * blockDim.x + threadIdx.x; i < n; i += stride) {
        float4 v = reinterpret_cast<const float4*>(src)[i];
        __half2* d2p = reinterpret_cast<__half2*>(dst) + i * 2;
        d2p[0] = __floats2half2_rn(v.x, v.y);
        d2p[1] = __floats2half2_rn(v.z, v.w);
    }
}

// ---------------------------------------------------------------------------
// cp.async helpers
// ---------------------------------------------------------------------------
__device__ __forceinline__ void cp_async16(void* smem_dst, const void* gsrc) {
    unsigned int sa = (unsigned int)__cvta_generic_to_shared(smem_dst);
    asm volatile("cp.async.cg.shared.global [%0], [%1], 16;\n" :: "r"(sa), "l"(gsrc));
}
__device__ __forceinline__ void cp_commit() {
    asm volatile("cp.async.commit_group;\n" ::);
}
template <int N>
__device__ __forceinline__ void cp_wait() {
    asm volatile("cp.async.wait_group %0;\n" :: "n"(N));
}

// ---------------------------------------------------------------------------
// fp16 GEMM core: C[0:64, n0:n0+128] = A[0:64, 0:512] @ W[512,512]
// BM=64, BN=128, BK=32, 3-stage cp.async pipeline, 128 threads (4 warps 2x2),
// warp tile 32x64 (2x4 wmma fp16 m16n16k16, fp32 accum). 4 CTAs/SM.
// ---------------------------------------------------------------------------
constexpr int ASTR_H = 40;    // As row stride (halves): 32 + 8 pad
constexpr int BSTR_H = 136;   // Bs row stride (halves): 128 + 8 pad
constexpr int STAGE_HALVES = 64 * ASTR_H + 32 * BSTR_H;    // 6912
constexpr int GEMM_SMEM = 3 * STAGE_HALVES * 2;            // 41472 bytes
constexpr int CSTR = 132;     // epilogue float staging stride

__device__ __forceinline__ void issue_stage_h(
    __half* stage, const __half* __restrict__ A, const __half* __restrict__ W,
    int n0, int k0, int tid)
{
    __half* As = stage;
    __half* Bs = stage + 64 * ASTR_H;
    #pragma unroll
    for (int t = 0; t < 2; t++) {                 // A: 64 rows x 4 chunks(8h)
        int j = tid + t * 128;
        int r = j >> 2, c = (j & 3) << 3;
        cp_async16(&As[r * ASTR_H + c], &A[(size_t)r * 512 + k0 + c]);
    }
    #pragma unroll
    for (int t = 0; t < 4; t++) {                 // B: 32 rows x 16 chunks(8h)
        int j = tid + t * 128;
        int rb = j >> 4, cb = (j & 15) << 3;
        cp_async16(&Bs[rb * BSTR_H + cb], &W[(size_t)(k0 + rb) * 512 + n0 + cb]);
    }
}

__device__ __forceinline__ void gemm_core_h(
    const __half* __restrict__ A, const __half* __restrict__ W,
    float* __restrict__ Cf, __half* __restrict__ Ch,
    const float* __restrict__ bias, int n0)
{
    extern __shared__ __align__(16) __half hsmem[];
    const int tid    = threadIdx.x;
    const int wid    = tid >> 5;
    const int warp_m = wid >> 1;     // 0..1 -> rows warp_m*32
    const int warp_n = wid & 1;      // 0..1 -> cols warp_n*64

    wmma::fragment<wmma::accumulator, 16, 16, 16, float> acc[2][4];
    #pragma unroll
    for (int i = 0; i < 2; i++)
        #pragma unroll
        for (int j = 0; j < 4; j++)
            wmma::fill_fragment(acc[i][j], 0.0f);

    #pragma unroll
    for (int s = 0; s < 2; s++) {
        issue_stage_h(hsmem + s * STAGE_HALVES, A, W, n0, s * 32, tid);
        cp_commit();
    }

    for (int it = 0; it < 16; it++) {
        cp_wait<1>();          // stage `it` resident
        __syncthreads();       // also guards buffer (it+2)%3 reuse
        if (it + 2 < 16)
            issue_stage_h(hsmem + ((it + 2) % 3) * STAGE_HALVES, A, W,
                          n0, (it + 2) * 32, tid);
        cp_commit();           // one group per iter keeps counts aligned

        __half* As = hsmem + (it % 3) * STAGE_HALVES;
        __half* Bs = As + 64 * ASTR_H;
        #pragma unroll
        for (int ks = 0; ks < 2; ks++) {
            wmma::fragment<wmma::matrix_a, 16, 16, 16, half, wmma::row_major> af[2];
            wmma::fragment<wmma::matrix_b, 16, 16, 16, half, wmma::row_major> bf[4];
            wmma::load_matrix_sync(af[0], &As[(warp_m * 32     ) * ASTR_H + ks * 16], ASTR_H);
            wmma::load_matrix_sync(af[1], &As[(warp_m * 32 + 16) * ASTR_H + ks * 16], ASTR_H);
            #pragma unroll
            for (int j = 0; j < 4; j++)
                wmma::load_matrix_sync(bf[j], &Bs[(ks * 16) * BSTR_H + warp_n * 64 + j * 16], BSTR_H);
            #pragma unroll
            for (int i = 0; i < 2; i++)
                #pragma unroll
                for (int j = 0; j < 4; j++)
                    wmma::mma_sync(acc[i][j], af[i], bf[j], acc[i][j]);
        }
    }
    __syncthreads();   // all compute done before epilogue smem reuse

    // Stage via smem (reuse pipeline buffer as float[64][CSTR])
    float (*Cs)[CSTR] = reinterpret_cast<float(*)[CSTR]>(hsmem);
    #pragma unroll
    for (int i = 0; i < 2; i++)
        #pragma unroll
        for (int j = 0; j < 4; j++)
            wmma::store_matrix_sync(
                &Cs[warp_m * 32 + i * 16][warp_n * 64 + j * 16],
                acc[i][j], CSTR, wmma::mem_row_major);
    __syncthreads();

    const int n4 = 64 * 32;                // 64 rows x 128 floats in float4 units
    if (Ch != nullptr) {
        for (int lin = tid; lin < n4; lin += 128) {
            int r = lin >> 5, c4 = (lin & 31) << 2;
            float4 v = *reinterpret_cast<const float4*>(&Cs[r][c4]);
            __half2* dst = reinterpret_cast<__half2*>(&Ch[(size_t)r * 512 + n0 + c4]);
            dst[0] = __floats2half2_rn(v.x, v.y);
            dst[1] = __floats2half2_rn(v.z, v.w);
        }
    } else {
        for (int lin = tid; lin < n4; lin += 128) {
            int r = lin >> 5, c4 = (lin & 31) << 2;
            float4 v = *reinterpret_cast<const float4*>(&Cs[r][c4]);
            v.x += bias[n0 + c4 + 0];
            v.y += bias[n0 + c4 + 1];
            v.z += bias[n0 + c4 + 2];
            v.w += bias[n0 + c4 + 3];
            *reinterpret_cast<float4*>(&Cf[(size_t)r * 512 + n0 + c4]) = v;
        }
    }
}

// Fused Q/K/V projection (+ global-latent K/V). grid = (4, 65, 3)
__global__ __launch_bounds__(128, 4)
void qkv_gemm(const __half* __restrict__ spatial, const __half* __restrict__ glat,
              const __half* __restrict__ Wq, const __half* __restrict__ Wk,
              const __half* __restrict__ Wv,
              __half* __restrict__ Q, __half* __restrict__ K, __half* __restrict__ V,
              __half* __restrict__ Kg, __half* __restrict__ Vg)
{
    const int z = blockIdx.z, y = blockIdx.y;
    const __half* W = (z == 0) ? Wq : (z == 1) ? Wk : Wv;
    if (y < 64) {
        const __half* A = spatial + (size_t)y * 64 * 512;
        __half* C = ((z == 0) ? Q : (z == 1) ? K : V) + (size_t)y * 64 * 512;
        gemm_core_h(A, W, nullptr, C, nullptr, blockIdx.x * 128);
    } else {
        if (z == 0) return;
        gemm_core_h(glat, W, nullptr, (z == 1) ? Kg : Vg, nullptr,
                    blockIdx.x * 128);
    }
}

// Output projection with bias. grid = (4, 64)
__global__ __launch_bounds__(128, 4)
void out_gemm(const __half* __restrict__ A, const __half* __restrict__ W,
              const float* __restrict__ bias, float* __restrict__ C)
{
    gemm_core_h(A + (size_t)blockIdx.y * 64 * 512, W,
                C + (size_t)blockIdx.y * 64 * 512, nullptr, bias,
                blockIdx.x * 128);
}

// ---------------------------------------------------------------------------
// Gather attention: one block per (b,l), one warp per head.
// 8-lane groups: each group handles one context with 16B (8-half) loads.
// ---------------------------------------------------------------------------
__global__ __launch_bounds__(256)
void attn_kernel(const __half* __restrict__ Q,   const __half* __restrict__ Ksp,
                 const __half* __restrict__ Vsp, const __half* __restrict__ Kg,
                 const __half* __restrict__ Vg,  const int*    __restrict__ topk,
                 const float*  __restrict__ dist,
                 const float*  __restrict__ log_sigma,
                 const float*  __restrict__ gbias_p,
                 __half* __restrict__ outh)
{
    const int bl   = blockIdx.x;
    const int b    = bl >> 11;            // L = 2048
    const int tid  = threadIdx.x;
    const int h    = tid >> 5;
    const int lane = tid & 31;
    const int g    = lane >> 3;           // group 0..3
    const int s    = lane & 7;            // sublane 0..7

    __shared__ const __half* kp[CTX];
    __shared__ const __half* vp[CTX];
    __shared__ float dist2[33];
    __shared__ float logits[HH][68];

    if (tid < CTX) {
        int c = tid;
        const __half *kq, *vq;
        if (c == 0) {
            kq = Ksp + (size_t)bl * DD;
            vq = Vsp + (size_t)bl * DD;
        } else if (c < 33) {
            int r = b * LL + topk[(size_t)bl * KK + (c - 1)];
            kq = Ksp + (size_t)r * DD;
            vq = Vsp + (size_t)r * DD;
        } else {
            int r = b * GG + (c - 33);
            kq = Kg + (size_t)r * DD;
            vq = Vg + (size_t)r * DD;
        }
        kp[c] = kq;
        vp[c] = vq;
        if (c < 33) {
            float d = (c == 0) ? 0.0f : dist[(size_t)bl * KK + (c - 1)];
            dist2[c] = d * d;
        }
    }
    __syncthreads();

    const float inv2s = 0.5f * __expf(-2.0f * log_sigma[h]);  // 1/(2*sigma^2)
    const float gb    = *gbias_p;
    const float scale = 0.125f;                               // 64^-0.5
    const int   off   = h * DHH + s * 8;    // 8-half slice for this sublane

    // Q slice: 8 halves -> 8 floats
    float qf[8];
    {
        float4 qv = *reinterpret_cast<const float4*>(Q + (size_t)bl * DD + off);
        const __half2* qh = reinterpret_cast<const __half2*>(&qv);
        #pragma unroll
        for (int i = 0; i < 4; i++) {
            float2 f = __half22float2(qh[i]);
            qf[2 * i]     = f.x;
            qf[2 * i + 1] = f.y;
        }
    }

    // Logits: 4 contexts per iteration (one per 8-lane group)
    #pragma unroll 4
    for (int c0 = 0; c0 < CTX; c0 += 4) {
        int  c     = c0 + g;
        bool valid = (c < CTX);
        float dot = 0.0f;
        if (valid) {
            float4 kv = *reinterpret_cast<const float4*>(kp[c] + off);
            const __half2* kh = reinterpret_cast<const __half2*>(&kv);
            #pragma unroll
            for (int i = 0; i < 4; i++) {
                float2 f = __half22float2(kh[i]);
                dot += qf[2 * i] * f.x + qf[2 * i + 1] * f.y;
            }
        }
        #pragma unroll
        for (int d = 4; d; d >>= 1)
            dot += __shfl_xor_sync(0xffffffffu, dot, d);
        if (s == 0 && valid)
            logits[h][c] = dot * scale + ((c < 33) ? -dist2[c] * inv2s : gb);
    }
    __syncwarp();

    // softmax over 65 entries (per-warp)
    float l0 = logits[h][lane];
    float l1 = logits[h][lane + 32];
    float l2 = (lane == 0) ? logits[h][64] : -1e30f;
    float m = fmaxf(fmaxf(l0, l1), l2);
    #pragma unroll
    for (int d = 16; d; d >>= 1)
        m = fmaxf(m, __shfl_xor_sync(0xffffffffu, m, d));
    float e0 = __expf(l0 - m);
    float e1 = __expf(l1 - m);
    float e2 = (lane == 0) ? __expf(l2 - m) : 0.0f;
    float sm = e0 + e1 + e2;
    #pragma unroll
    for (int d = 16; d; d >>= 1)
        sm += __shfl_xor_sync(0xffffffffu, sm, d);
    float inv = 1.0f / sm;
    logits[h][lane]      = e0 * inv;
    logits[h][lane + 32] = e1 * inv;
    if (lane == 0) logits[h][64] = e2 * inv;
    __syncwarp();

    // Weighted V sum: group g handles contexts c = 4*i + g; lane holds 8 dims.
    float acc[8];
    #pragma unroll
    for (int i = 0; i < 8; i++) acc[i] = 0.0f;

    #pragma unroll 4
    for (int i = 0; i < 17; i++) {
        int c = 4 * i + g;
        if (c < CTX) {
            float  p  = logits[h][c];
            float4 vv = *reinterpret_cast<const float4*>(vp[c] + off);
            const __half2* vh = reinterpret_cast<const __half2*>(&vv);
            #pragma unroll
            for (int k = 0; k < 4; k++) {
                float2 f = __half22float2(vh[k]);
                acc[2 * k]     += p * f.x;
                acc[2 * k + 1] += p * f.y;
            }
        }
    }
    // Reduce across the 4 groups (same dims, different contexts)
    #pragma unroll
    for (int k = 0; k < 8; k++) {
        acc[k] += __shfl_xor_sync(0xffffffffu, acc[k], 8);
        acc[k] += __shfl_xor_sync(0xffffffffu, acc[k], 16);
    }
    if (g == 0) {
        __half2 hv[4];
        #pragma unroll
        for (int k = 0; k < 4; k++)
            hv[k] = __floats2half2_rn(acc[2 * k], acc[2 * k + 1]);
        *reinterpret_cast<uint4*>(outh + (size_t)bl * DD + off) =
            *reinterpret_cast<const uint4*>(hv);
    }
}

// ---------------------------------------------------------------------------
extern "C" void kernel_launch(void* const* d_in, const int* in_sizes, int n_in,
                              void* d_out, int out_size)
{
    const float* spatial = (const float*)d_in[0];
    const int*   topk    = (const int*)  d_in[1];
    const float* dist    = (const float*)d_in[2];
    const float* glat    = (const float*)d_in[3];
    const float* Wq      = (const float*)d_in[4];
    const float* Wk      = (const float*)d_in[5];
    const float* Wv      = (const float*)d_in[6];
    const float* Wo      = (const float*)d_in[7];
    const float* bo      = (const float*)d_in[8];
    const float* lsig    = (const float*)d_in[9];
    const float* gbias   = (const float*)d_in[10];
    float* out = (float*)d_out;

    __half *Qp, *Kp, *Vp, *Ah, *Kgp, *Vgp;
    __half *sph, *glh, *wqh, *wkh, *wvh, *woh;
    cudaGetSymbolAddress((void**)&Qp,  g_Qh);
    cudaGetSymbolAddress((void**)&Kp,  g_Kh);
    cudaGetSymbolAddress((void**)&Vp,  g_Vh);
    cudaGetSymbolAddress((void**)&Ah,  g_attnh);
    cudaGetSymbolAddress((void**)&Kgp, g_Kgh);
    cudaGetSymbolAddress((void**)&Vgp, g_Vgh);
    cudaGetSymbolAddress((void**)&sph, g_sp_h);
    cudaGetSymbolAddress((void**)&glh, g_gl_h);
    cudaGetSymbolAddress((void**)&wqh, g_Wq_h);
    cudaGetSymbolAddress((void**)&wkh, g_Wk_h);
    cudaGetSymbolAddress((void**)&wvh, g_Wv_h);
    cudaGetSymbolAddress((void**)&woh, g_Wo_h);

    cudaFuncSetAttribute(qkv_gemm, cudaFuncAttributeMaxDynamicSharedMemorySize, GEMM_SMEM);
    cudaFuncSetAttribute(out_gemm, cudaFuncAttributeMaxDynamicSharedMemorySize, GEMM_SMEM);

    // Convert all GEMM inputs to fp16 (one pass)
    dim3 cvt_grid(64, 6);
    to_half_all<<<cvt_grid, 256>>>(
        spatial, sph, BL * DD / 4,
        Wq, wqh, DD * DD / 4,
        Wk, wkh, DD * DD / 4,
        Wv, wvh, DD * DD / 4,
        Wo, woh, DD * DD / 4,
        glat, glh, BB * GG * DD / 4);

    dim3 qkv_grid(4, 65, 3);
    qkv_gemm<<<qkv_grid, 128, GEMM_SMEM>>>(sph, glh, wqh, wkh, wvh,
                                           Qp, Kp, Vp, Kgp, Vgp);

    attn_kernel<<<BL, 256>>>(Qp, Kp, Vp, Kgp, Vgp, topk, dist, lsig, gbias, Ah);

    dim3 out_grid(4, 64);
    out_gemm<<<out_grid, 128, GEMM_SMEM>>>(Ah, woh, bo, out);
}